// round 2
// baseline (speedup 1.0000x reference)
#include <cuda_runtime.h>
#include <math.h>

#define NN 100000
#define NE 1600000
#define F0 500
#define F1 128
#define F2 64
#define F3 40

// Static scratch (allocation-free rule: __device__ globals)
__device__ int   g_deg [NN];
__device__ float g_dinv[NN];
__device__ __align__(16) float g_bufA[(size_t)NN * F1];
__device__ __align__(16) float g_bufB[(size_t)NN * F1];
__device__ __align__(16) float g_bufC[(size_t)NN * F1];

// ---------------- degree / dinv ----------------
__global__ void deg_init_k(int n) {
    int i = blockIdx.x * blockDim.x + threadIdx.x;
    if (i < n) g_deg[i] = 1;                       // self-loop
}
__global__ void deg_count_k(const int* __restrict__ dst, int e) {
    int i = blockIdx.x * blockDim.x + threadIdx.x;
    if (i < e) atomicAdd(&g_deg[dst[i]], 1);
}
__global__ void dinv_k(int n) {
    int i = blockIdx.x * blockDim.x + threadIdx.x;
    if (i < n) g_dinv[i] = rsqrtf((float)g_deg[i]);
}

// ---------------- tiled GEMM with fused row-scale epilogue ----------------
// Computes hs[r,c] = (X[r,:] @ W[:,c]) * dinv[r]; also writes the same value
// into `ini` (the aggregation buffer's self-loop initialization).
// BN == full output width C.
template<int BM, int BN, int BK, int TM, int TN>
__global__ void gemm_scale_k(const float* __restrict__ X, const float* __restrict__ W,
                             float* __restrict__ hs, float* __restrict__ ini,
                             int M, int K) {
    __shared__ float Xs[BM][BK + 1];
    __shared__ float Ws[BK][BN];
    constexpr int NT = (BM / TM) * (BN / TN);
    const int tid = threadIdx.x;
    const int tx  = tid % (BN / TN);
    const int ty  = tid / (BN / TN);
    const int row0 = blockIdx.x * BM;

    float acc[TM][TN];
#pragma unroll
    for (int i = 0; i < TM; i++)
#pragma unroll
        for (int j = 0; j < TN; j++) acc[i][j] = 0.f;

    for (int k0 = 0; k0 < K; k0 += BK) {
        for (int i = tid; i < BM * BK; i += NT) {
            int r = i / BK, kk = i % BK;
            int gr = row0 + r; if (gr >= M) gr = M - 1;
            int gk = k0 + kk;
            Xs[r][kk] = (gk < K) ? X[(size_t)gr * K + gk] : 0.f;
        }
        for (int i = tid; i < BK * BN; i += NT) {
            int kk = i / BN, c = i % BN;
            int gk = k0 + kk;
            Ws[kk][c] = (gk < K) ? W[(size_t)gk * BN + c] : 0.f;
        }
        __syncthreads();
#pragma unroll
        for (int kk = 0; kk < BK; kk++) {
            float a[TM], b[TN];
#pragma unroll
            for (int i = 0; i < TM; i++) a[i] = Xs[ty * TM + i][kk];
#pragma unroll
            for (int j = 0; j < TN; j++) b[j] = Ws[kk][tx * TN + j];
#pragma unroll
            for (int i = 0; i < TM; i++)
#pragma unroll
                for (int j = 0; j < TN; j++) acc[i][j] += a[i] * b[j];
        }
        __syncthreads();
    }

#pragma unroll
    for (int i = 0; i < TM; i++) {
        int r = row0 + ty * TM + i;
        if (r < M) {
            float dv = g_dinv[r];
#pragma unroll
            for (int j = 0; j < TN; j++) {
                float v = acc[i][j] * dv;
                size_t idx = (size_t)r * BN + tx * TN + j;
                hs[idx]  = v;
                ini[idx] = v;
            }
        }
    }
}

// ---------------- edge scatter-add ----------------
// block = (C/4, EB): threadIdx.x = float4 chunk within feature row,
// threadIdx.y = edge within block. agg[dst] += hs[src].
template<int C, int EB>
__global__ void scatter_k(const int* __restrict__ src, const int* __restrict__ dst,
                          const float* __restrict__ hs, float* __restrict__ agg, int E) {
    constexpr int CH = C / 4;
    int e = blockIdx.x * EB + threadIdx.y;
    if (e >= E) return;
    int s = src[e];
    int d = dst[e];
    int c = threadIdx.x;
    float4 v = reinterpret_cast<const float4*>(hs)[(size_t)s * CH + c];
    float* p = agg + (size_t)d * C + c * 4;
    atomicAdd(p + 0, v.x);
    atomicAdd(p + 1, v.y);
    atomicAdd(p + 2, v.z);
    atomicAdd(p + 3, v.w);
}

// ---------------- finalize: out = [relu](agg*dinv + b) ----------------
template<bool RELU, int C>
__global__ void finalize_k(const float* __restrict__ agg, const float* __restrict__ b,
                           float* __restrict__ out, int n) {
    int i = blockIdx.x * blockDim.x + threadIdx.x;
    if (i >= n * C) return;
    int r = i / C, c = i % C;
    float v = agg[i] * g_dinv[r] + b[c];
    if (RELU) v = fmaxf(v, 0.f);
    out[i] = v;
}

// ---------------- final layer: bias + log_softmax (40 cols, one warp/row) ----
__global__ void lsm_k(const float* __restrict__ agg, const float* __restrict__ b,
                      float* __restrict__ out, int n) {
    int gid  = blockIdx.x * blockDim.x + threadIdx.x;
    int row  = gid >> 5;
    int lane = threadIdx.x & 31;
    if (row >= n) return;
    float dv = g_dinv[row];
    const float* rp = agg + (size_t)row * F3;
    float v0 = rp[lane] * dv + b[lane];
    float v1 = (lane < F3 - 32) ? rp[lane + 32] * dv + b[lane + 32] : -INFINITY;
    float m = fmaxf(v0, v1);
#pragma unroll
    for (int o = 16; o; o >>= 1) m = fmaxf(m, __shfl_xor_sync(0xffffffffu, m, o));
    float s = expf(v0 - m) + ((lane < F3 - 32) ? expf(v1 - m) : 0.f);
#pragma unroll
    for (int o = 16; o; o >>= 1) s += __shfl_xor_sync(0xffffffffu, s, o);
    float lse = logf(s) + m;
    float* op = out + (size_t)row * F3;
    op[lane] = v0 - lse;
    if (lane < F3 - 32) op[lane + 32] = v1 - lse;
}

extern "C" void kernel_launch(void* const* d_in, const int* in_sizes, int n_in,
                              void* d_out, int out_size) {
    const float* x   = (const float*)d_in[0];
    const int*   ei  = (const int*)d_in[1];     // int32! (JAX x64 disabled)
    const float* W1  = (const float*)d_in[2];
    const float* b1  = (const float*)d_in[3];
    const float* W2  = (const float*)d_in[4];
    const float* b2  = (const float*)d_in[5];
    const float* W4  = (const float*)d_in[6];
    const float* b4  = (const float*)d_in[7];
    float* out = (float*)d_out;

    const int N = in_sizes[0] / F0;       // 100000
    const int E = in_sizes[1] / 2;        // 1600000
    const int* src = ei;
    const int* dst = ei + E;

    float *A, *B, *C;
    cudaGetSymbolAddress((void**)&A, g_bufA);
    cudaGetSymbolAddress((void**)&B, g_bufB);
    cudaGetSymbolAddress((void**)&C, g_bufC);

    // degrees
    deg_init_k <<<(N + 255) / 256, 256>>>(N);
    deg_count_k<<<(E + 255) / 256, 256>>>(dst, E);
    dinv_k     <<<(N + 255) / 256, 256>>>(N);

    // ---- layer 1: 500 -> 128 ----
    gemm_scale_k<64, 128, 16, 8, 4><<<(N + 63) / 64, 256>>>(x, W1, A, B, N, F0);
    scatter_k<128, 8><<<(E + 7) / 8, dim3(32, 8)>>>(src, dst, A, B, E);
    finalize_k<true, 128><<<((size_t)N * 128 + 255) / 256, 256>>>(B, b1, A, N);

    // ---- layer 2: 128 -> 64 ----
    gemm_scale_k<64, 64, 16, 4, 4><<<(N + 63) / 64, 256>>>(A, W2, B, C, N, F1);
    scatter_k<64, 16><<<(E + 15) / 16, dim3(16, 16)>>>(src, dst, B, C, E);
    finalize_k<true, 64><<<((size_t)N * 64 + 255) / 256, 256>>>(C, b2, A, N);

    // ---- layer 3: 64 -> 40 + log_softmax ----
    gemm_scale_k<128, 40, 16, 8, 5><<<(N + 127) / 128, 128>>>(A, W4, B, C, N, F2);
    scatter_k<40, 16><<<(E + 15) / 16, dim3(10, 16)>>>(src, dst, B, C, E);
    lsm_k<<<(N * 32 + 255) / 256, 256>>>(C, b4, out, N);
}

// round 3
// speedup vs baseline: 1.6068x; 1.6068x over previous
#include <cuda_runtime.h>
#include <math.h>

#define NN 100000
#define NE 1600000
#define F0 500
#define F1 128
#define F2 64
#define F3 40

// Static scratch (allocation-free rule: __device__ globals)
__device__ int   g_deg [NN];
__device__ float g_dinv[NN];
__device__ __align__(16) float g_bufA[(size_t)NN * F1];
__device__ __align__(16) float g_bufB[(size_t)NN * F1];
__device__ __align__(16) float g_bufC[(size_t)NN * F1];

// ---------------- degree / dinv ----------------
__global__ void deg_init_k(int n) {
    int i = blockIdx.x * blockDim.x + threadIdx.x;
    if (i < n) g_deg[i] = 1;                       // self-loop
}
__global__ void deg_count_k(const int* __restrict__ dst, int e) {
    int i = blockIdx.x * blockDim.x + threadIdx.x;
    if (i < e) atomicAdd(&g_deg[dst[i]], 1);
}
__global__ void dinv_k(int n) {
    int i = blockIdx.x * blockDim.x + threadIdx.x;
    if (i < n) g_dinv[i] = rsqrtf((float)g_deg[i]);
}

// ---------------- v2 GEMM: transposed A smem, all-vector LDS ----------------
// hs[r,c] = (X[r,:] @ W[:,c]) * dinv[r]; ini gets the same value (self-loop init).
// Requires: TM==8, TN in {4,8}, BN == output width, K % 4 == 0.
template<int BM, int BN, int BK, int TM, int TN>
__global__ void gemm_v2_k(const float* __restrict__ X, const float* __restrict__ W,
                          float* __restrict__ hs, float* __restrict__ ini,
                          int M, int K) {
    constexpr int NT  = (BM / TM) * (BN / TN);
    constexpr int BMP = BM + 4;                    // keep 16B alignment of rows
    __shared__ float Xs[BK][BMP];
    __shared__ float Ws[BK][BN];

    const int tid  = threadIdx.x;
    const int tx   = tid % (BN / TN);
    const int ty   = tid / (BN / TN);
    const int row0 = blockIdx.x * BM;

    float acc[TM][TN];
#pragma unroll
    for (int i = 0; i < TM; i++)
#pragma unroll
        for (int j = 0; j < TN; j++) acc[i][j] = 0.f;

    for (int k0 = 0; k0 < K; k0 += BK) {
        // ---- A tile (transposed into Xs[k][r]) ----
        if (k0 + BK <= K) {
#pragma unroll
            for (int idx = tid; idx < BM * BK / 4; idx += NT) {
                int r  = idx / (BK / 4);
                int kv = idx % (BK / 4);
                int gr = row0 + r; if (gr >= M) gr = M - 1;
                float4 v = *(const float4*)&X[(size_t)gr * K + k0 + kv * 4];
                Xs[kv * 4 + 0][r] = v.x;
                Xs[kv * 4 + 1][r] = v.y;
                Xs[kv * 4 + 2][r] = v.z;
                Xs[kv * 4 + 3][r] = v.w;
            }
        } else {                                    // K tail (e.g. 500 % 16)
            for (int idx = tid; idx < BM * BK; idx += NT) {
                int r = idx / BK, kk = idx % BK;
                int gr = row0 + r; if (gr >= M) gr = M - 1;
                int gk = k0 + kk;
                Xs[kk][r] = (gk < K) ? X[(size_t)gr * K + gk] : 0.f;
            }
        }
        // ---- W tile ----
#pragma unroll
        for (int idx = tid; idx < BK * BN / 4; idx += NT) {
            int kk = idx / (BN / 4);
            int cv = idx % (BN / 4);
            int gk = k0 + kk;
            float4 v = (gk < K) ? *(const float4*)&W[(size_t)gk * BN + cv * 4]
                                : make_float4(0.f, 0.f, 0.f, 0.f);
            *(float4*)&Ws[kk][cv * 4] = v;
        }
        __syncthreads();

#pragma unroll
        for (int kk = 0; kk < BK; kk++) {
            float a[TM], b[TN];
#pragma unroll
            for (int i4 = 0; i4 < TM / 4; i4++)
                *(float4*)&a[i4 * 4] = *(const float4*)&Xs[kk][ty * TM + i4 * 4];
#pragma unroll
            for (int j4 = 0; j4 < TN / 4; j4++)
                *(float4*)&b[j4 * 4] = *(const float4*)&Ws[kk][tx * TN + j4 * 4];
#pragma unroll
            for (int i = 0; i < TM; i++)
#pragma unroll
                for (int j = 0; j < TN; j++) acc[i][j] += a[i] * b[j];
        }
        __syncthreads();
    }

#pragma unroll
    for (int i = 0; i < TM; i++) {
        int r = row0 + ty * TM + i;
        if (r < M) {
            float dv = g_dinv[r];
#pragma unroll
            for (int j4 = 0; j4 < TN / 4; j4++) {
                float4 v;
                v.x = acc[i][j4 * 4 + 0] * dv;
                v.y = acc[i][j4 * 4 + 1] * dv;
                v.z = acc[i][j4 * 4 + 2] * dv;
                v.w = acc[i][j4 * 4 + 3] * dv;
                size_t idx = (size_t)r * BN + tx * TN + j4 * 4;
                *(float4*)&hs[idx]  = v;
                *(float4*)&ini[idx] = v;
            }
        }
    }
}

// ---------------- v1 GEMM kept for the irregular 64->40 layer ----------------
template<int BM, int BN, int BK, int TM, int TN>
__global__ void gemm_scale_k(const float* __restrict__ X, const float* __restrict__ W,
                             float* __restrict__ hs, float* __restrict__ ini,
                             int M, int K) {
    __shared__ float Xs[BM][BK + 1];
    __shared__ float Ws[BK][BN];
    constexpr int NT = (BM / TM) * (BN / TN);
    const int tid = threadIdx.x;
    const int tx  = tid % (BN / TN);
    const int ty  = tid / (BN / TN);
    const int row0 = blockIdx.x * BM;

    float acc[TM][TN];
#pragma unroll
    for (int i = 0; i < TM; i++)
#pragma unroll
        for (int j = 0; j < TN; j++) acc[i][j] = 0.f;

    for (int k0 = 0; k0 < K; k0 += BK) {
        for (int i = tid; i < BM * BK; i += NT) {
            int r = i / BK, kk = i % BK;
            int gr = row0 + r; if (gr >= M) gr = M - 1;
            int gk = k0 + kk;
            Xs[r][kk] = (gk < K) ? X[(size_t)gr * K + gk] : 0.f;
        }
        for (int i = tid; i < BK * BN; i += NT) {
            int kk = i / BN, c = i % BN;
            int gk = k0 + kk;
            Ws[kk][c] = (gk < K) ? W[(size_t)gk * BN + c] : 0.f;
        }
        __syncthreads();
#pragma unroll
        for (int kk = 0; kk < BK; kk++) {
            float a[TM], b[TN];
#pragma unroll
            for (int i = 0; i < TM; i++) a[i] = Xs[ty * TM + i][kk];
#pragma unroll
            for (int j = 0; j < TN; j++) b[j] = Ws[kk][tx * TN + j];
#pragma unroll
            for (int i = 0; i < TM; i++)
#pragma unroll
                for (int j = 0; j < TN; j++) acc[i][j] += a[i] * b[j];
        }
        __syncthreads();
    }

#pragma unroll
    for (int i = 0; i < TM; i++) {
        int r = row0 + ty * TM + i;
        if (r < M) {
            float dv = g_dinv[r];
#pragma unroll
            for (int j = 0; j < TN; j++) {
                float v = acc[i][j] * dv;
                size_t idx = (size_t)r * BN + tx * TN + j;
                hs[idx]  = v;
                ini[idx] = v;
            }
        }
    }
}

// ---------------- edge scatter-add with vector red ----------------
__device__ __forceinline__ void red_add_v4(float* p, float4 v) {
    asm volatile("red.global.add.v4.f32 [%0], {%1, %2, %3, %4};"
                 :: "l"(p), "f"(v.x), "f"(v.y), "f"(v.z), "f"(v.w) : "memory");
}

template<int C, int EB>
__global__ void scatter_k(const int* __restrict__ src, const int* __restrict__ dst,
                          const float* __restrict__ hs, float* __restrict__ agg, int E) {
    constexpr int CH = C / 4;
    int e = blockIdx.x * EB + threadIdx.y;
    if (e >= E) return;
    int s = src[e];
    int d = dst[e];
    int c = threadIdx.x;
    float4 v = reinterpret_cast<const float4*>(hs)[(size_t)s * CH + c];
    red_add_v4(agg + (size_t)d * C + c * 4, v);
}

// ---------------- finalize: out = [relu](agg*dinv + b) ----------------
template<bool RELU, int C>
__global__ void finalize_k(const float* __restrict__ agg, const float* __restrict__ b,
                           float* __restrict__ out, int n) {
    int i = blockIdx.x * blockDim.x + threadIdx.x;
    if (i >= n * C) return;
    int r = i / C, c = i % C;
    float v = agg[i] * g_dinv[r] + b[c];
    if (RELU) v = fmaxf(v, 0.f);
    out[i] = v;
}

// ---------------- final layer: bias + log_softmax (40 cols, one warp/row) ----
__global__ void lsm_k(const float* __restrict__ agg, const float* __restrict__ b,
                      float* __restrict__ out, int n) {
    int gid  = blockIdx.x * blockDim.x + threadIdx.x;
    int row  = gid >> 5;
    int lane = threadIdx.x & 31;
    if (row >= n) return;
    float dv = g_dinv[row];
    const float* rp = agg + (size_t)row * F3;
    float v0 = rp[lane] * dv + b[lane];
    float v1 = (lane < F3 - 32) ? rp[lane + 32] * dv + b[lane + 32] : -INFINITY;
    float m = fmaxf(v0, v1);
#pragma unroll
    for (int o = 16; o; o >>= 1) m = fmaxf(m, __shfl_xor_sync(0xffffffffu, m, o));
    float s = expf(v0 - m) + ((lane < F3 - 32) ? expf(v1 - m) : 0.f);
#pragma unroll
    for (int o = 16; o; o >>= 1) s += __shfl_xor_sync(0xffffffffu, s, o);
    float lse = logf(s) + m;
    float* op = out + (size_t)row * F3;
    op[lane] = v0 - lse;
    if (lane < F3 - 32) op[lane + 32] = v1 - lse;
}

extern "C" void kernel_launch(void* const* d_in, const int* in_sizes, int n_in,
                              void* d_out, int out_size) {
    const float* x   = (const float*)d_in[0];
    const int*   ei  = (const int*)d_in[1];     // int32 (JAX x64 disabled)
    const float* W1  = (const float*)d_in[2];
    const float* b1  = (const float*)d_in[3];
    const float* W2  = (const float*)d_in[4];
    const float* b2  = (const float*)d_in[5];
    const float* W4  = (const float*)d_in[6];
    const float* b4  = (const float*)d_in[7];
    float* out = (float*)d_out;

    const int N = in_sizes[0] / F0;       // 100000
    const int E = in_sizes[1] / 2;        // 1600000
    const int* src = ei;
    const int* dst = ei + E;

    float *A, *B, *C;
    cudaGetSymbolAddress((void**)&A, g_bufA);
    cudaGetSymbolAddress((void**)&B, g_bufB);
    cudaGetSymbolAddress((void**)&C, g_bufC);

    // degrees
    deg_init_k <<<(N + 255) / 256, 256>>>(N);
    deg_count_k<<<(E + 255) / 256, 256>>>(dst, E);
    dinv_k     <<<(N + 255) / 256, 256>>>(N);

    // ---- layer 1: 500 -> 128 ----
    gemm_v2_k<128, 128, 16, 8, 8><<<(N + 127) / 128, 256>>>(x, W1, A, B, N, F0);
    scatter_k<128, 8><<<(E + 7) / 8, dim3(32, 8)>>>(src, dst, A, B, E);
    finalize_k<true, 128><<<((size_t)N * 128 + 255) / 256, 256>>>(B, b1, A, N);

    // ---- layer 2: 128 -> 64 ----
    gemm_v2_k<128, 64, 16, 8, 4><<<(N + 127) / 128, 256>>>(A, W2, B, C, N, F1);
    scatter_k<64, 16><<<(E + 15) / 16, dim3(16, 16)>>>(src, dst, B, C, E);
    finalize_k<true, 64><<<((size_t)N * 64 + 255) / 256, 256>>>(C, b2, A, N);

    // ---- layer 3: 64 -> 40 + log_softmax ----
    gemm_scale_k<128, 40, 16, 8, 5><<<(N + 127) / 128, 128>>>(A, W4, B, C, N, F2);
    scatter_k<40, 16><<<(E + 15) / 16, dim3(10, 16)>>>(src, dst, B, C, E);
    lsm_k<<<(N * 32 + 255) / 256, 256>>>(C, b4, out, N);
}

// round 4
// speedup vs baseline: 2.2029x; 1.3710x over previous
#include <cuda_runtime.h>
#include <math.h>

#define NN 100000
#define NE 1600000
#define F0 500
#define F1 128
#define F2 64
#define F3 40

// Static scratch (allocation-free rule: __device__ globals)
__device__ int   g_deg [NN];
__device__ float g_dinv[NN];
__device__ __align__(16) float g_bufA[(size_t)NN * F1];
__device__ __align__(16) float g_bufB[(size_t)NN * F1];
__device__ __align__(16) float g_bufC[(size_t)NN * F1];

// ---------------- degree / dinv ----------------
__global__ void deg_init_k(int n) {
    int i = blockIdx.x * blockDim.x + threadIdx.x;
    if (i < n) g_deg[i] = 1;                       // self-loop
}
__global__ void deg_count_k(const int* __restrict__ dst, int e) {
    int i = blockIdx.x * blockDim.x + threadIdx.x;
    if (i < e) atomicAdd(&g_deg[dst[i]], 1);
}
__global__ void dinv_k(int n) {
    int i = blockIdx.x * blockDim.x + threadIdx.x;
    if (i < n) g_dinv[i] = rsqrtf((float)g_deg[i]);
}

// ---------------- tf32 tensor-core GEMM (layer 1) ----------------
__device__ __forceinline__ unsigned f2tf32(float x) {
    unsigned r;
    asm("cvt.rna.tf32.f32 %0, %1;" : "=r"(r) : "f"(x));
    return r;
}
__device__ __forceinline__ void mma_tf32(float* d, const unsigned* a, const unsigned* b) {
    asm volatile(
        "mma.sync.aligned.m16n8k8.row.col.f32.tf32.tf32.f32 "
        "{%0,%1,%2,%3},{%4,%5,%6,%7},{%8,%9},{%0,%1,%2,%3};"
        : "+f"(d[0]), "+f"(d[1]), "+f"(d[2]), "+f"(d[3])
        : "r"(a[0]), "r"(a[1]), "r"(a[2]), "r"(a[3]), "r"(b[0]), "r"(b[1]));
}

// BM=128, BN=128, BK=32, 256 threads (8 warps), warp tile 32x64.
// hs[r,c] = (X[r,:] @ W[:,c]) * dinv[r]; ini gets the same value.
__global__ void __launch_bounds__(256) gemm_tf32_k(
        const float* __restrict__ X, const float* __restrict__ W,
        float* __restrict__ hs, float* __restrict__ ini, int M, int K) {
    constexpr int BM = 128, BN = 128, BK = 32;
    constexpr int BKP = BK + 1;     // 33: A row pad
    constexpr int BNP = BN + 4;     // 132: B row pad
    __shared__ unsigned Xs[BM][BKP];
    __shared__ unsigned Ws[BK][BNP];

    const int tid    = threadIdx.x;
    const int lane   = tid & 31;
    const int wid    = tid >> 5;
    const int warp_m = wid & 3;      // 0..3  -> 32-row strip
    const int warp_n = wid >> 2;     // 0..1  -> 64-col strip
    const int row0   = blockIdx.x * BM;
    const int lq     = lane >> 2;    // lane/4
    const int lr     = lane & 3;     // lane%4

    float acc[2][8][4];
#pragma unroll
    for (int i = 0; i < 2; i++)
#pragma unroll
        for (int j = 0; j < 8; j++)
#pragma unroll
            for (int t = 0; t < 4; t++) acc[i][j][t] = 0.f;

    const int nchunk = (K + BK - 1) / BK;
    for (int kc = 0; kc < nchunk; kc++) {
        const int k0 = kc * BK;
        // ---- A tile: 128x32, 4 float4 per thread ----
        if (k0 + BK <= K) {
#pragma unroll
            for (int it = 0; it < 4; it++) {
                int idx = tid + it * 256;            // 0..1023 float4 slots
                int r   = idx >> 3;                  // /8
                int kv  = idx & 7;                   // %8
                int gr  = row0 + r; if (gr >= M) gr = M - 1;
                float4 v = *(const float4*)&X[(size_t)gr * K + k0 + kv * 4];
                Xs[r][kv * 4 + 0] = f2tf32(v.x);
                Xs[r][kv * 4 + 1] = f2tf32(v.y);
                Xs[r][kv * 4 + 2] = f2tf32(v.z);
                Xs[r][kv * 4 + 3] = f2tf32(v.w);
            }
        } else {                                     // K tail (500 % 32 = 20)
            for (int idx = tid; idx < BM * BK; idx += 256) {
                int r = idx >> 5, kk = idx & 31;
                int gr = row0 + r; if (gr >= M) gr = M - 1;
                int gk = k0 + kk;
                Xs[r][kk] = (gk < K) ? f2tf32(X[(size_t)gr * K + gk]) : 0u;
            }
        }
        // ---- B tile: 32x128, 4 float4 per thread ----
#pragma unroll
        for (int it = 0; it < 4; it++) {
            int idx = tid + it * 256;                // 0..1023 float4 slots
            int kk  = idx >> 5;                      // /32
            int cv  = idx & 31;                      // %32
            int gk  = k0 + kk;
            float4 v = (gk < K) ? *(const float4*)&W[(size_t)gk * BN + cv * 4]
                                : make_float4(0.f, 0.f, 0.f, 0.f);
            Ws[kk][cv * 4 + 0] = f2tf32(v.x);
            Ws[kk][cv * 4 + 1] = f2tf32(v.y);
            Ws[kk][cv * 4 + 2] = f2tf32(v.z);
            Ws[kk][cv * 4 + 3] = f2tf32(v.w);
        }
        __syncthreads();

#pragma unroll
        for (int ks = 0; ks < 4; ks++) {
            const int kb = ks * 8;
            unsigned a[2][4], b[8][2];
#pragma unroll
            for (int i = 0; i < 2; i++) {
                int r = warp_m * 32 + i * 16;
                a[i][0] = Xs[r + lq    ][kb + lr    ];
                a[i][1] = Xs[r + lq + 8][kb + lr    ];
                a[i][2] = Xs[r + lq    ][kb + lr + 4];
                a[i][3] = Xs[r + lq + 8][kb + lr + 4];
            }
#pragma unroll
            for (int j = 0; j < 8; j++) {
                int n = warp_n * 64 + j * 8 + lq;
                b[j][0] = Ws[kb + lr    ][n];
                b[j][1] = Ws[kb + lr + 4][n];
            }
#pragma unroll
            for (int i = 0; i < 2; i++)
#pragma unroll
                for (int j = 0; j < 8; j++) mma_tf32(acc[i][j], a[i], b[j]);
        }
        __syncthreads();
    }

    // ---- epilogue: scale by dinv[row], write hs and ini ----
#pragma unroll
    for (int i = 0; i < 2; i++) {
        int r_lo = row0 + warp_m * 32 + i * 16 + lq;
        int r_hi = r_lo + 8;
        float dv_lo = (r_lo < M) ? g_dinv[r_lo] : 0.f;
        float dv_hi = (r_hi < M) ? g_dinv[r_hi] : 0.f;
#pragma unroll
        for (int j = 0; j < 8; j++) {
            int c = warp_n * 64 + j * 8 + lr * 2;
            if (r_lo < M) {
                float2 v = make_float2(acc[i][j][0] * dv_lo, acc[i][j][1] * dv_lo);
                size_t idx = (size_t)r_lo * BN + c;
                *(float2*)&hs[idx]  = v;
                *(float2*)&ini[idx] = v;
            }
            if (r_hi < M) {
                float2 v = make_float2(acc[i][j][2] * dv_hi, acc[i][j][3] * dv_hi);
                size_t idx = (size_t)r_hi * BN + c;
                *(float2*)&hs[idx]  = v;
                *(float2*)&ini[idx] = v;
            }
        }
    }
}

// ---------------- v2 FFMA GEMM (layer 2) ----------------
template<int BM, int BN, int BK, int TM, int TN>
__global__ void gemm_v2_k(const float* __restrict__ X, const float* __restrict__ W,
                          float* __restrict__ hs, float* __restrict__ ini,
                          int M, int K) {
    constexpr int NT  = (BM / TM) * (BN / TN);
    constexpr int BMP = BM + 4;
    __shared__ float Xs[BK][BMP];
    __shared__ float Ws[BK][BN];

    const int tid  = threadIdx.x;
    const int tx   = tid % (BN / TN);
    const int ty   = tid / (BN / TN);
    const int row0 = blockIdx.x * BM;

    float acc[TM][TN];
#pragma unroll
    for (int i = 0; i < TM; i++)
#pragma unroll
        for (int j = 0; j < TN; j++) acc[i][j] = 0.f;

    for (int k0 = 0; k0 < K; k0 += BK) {
        if (k0 + BK <= K) {
#pragma unroll
            for (int idx = tid; idx < BM * BK / 4; idx += NT) {
                int r  = idx / (BK / 4);
                int kv = idx % (BK / 4);
                int gr = row0 + r; if (gr >= M) gr = M - 1;
                float4 v = *(const float4*)&X[(size_t)gr * K + k0 + kv * 4];
                Xs[kv * 4 + 0][r] = v.x;
                Xs[kv * 4 + 1][r] = v.y;
                Xs[kv * 4 + 2][r] = v.z;
                Xs[kv * 4 + 3][r] = v.w;
            }
        } else {
            for (int idx = tid; idx < BM * BK; idx += NT) {
                int r = idx / BK, kk = idx % BK;
                int gr = row0 + r; if (gr >= M) gr = M - 1;
                int gk = k0 + kk;
                Xs[kk][r] = (gk < K) ? X[(size_t)gr * K + gk] : 0.f;
            }
        }
#pragma unroll
        for (int idx = tid; idx < BK * BN / 4; idx += NT) {
            int kk = idx / (BN / 4);
            int cv = idx % (BN / 4);
            int gk = k0 + kk;
            float4 v = (gk < K) ? *(const float4*)&W[(size_t)gk * BN + cv * 4]
                                : make_float4(0.f, 0.f, 0.f, 0.f);
            *(float4*)&Ws[kk][cv * 4] = v;
        }
        __syncthreads();

#pragma unroll
        for (int kk = 0; kk < BK; kk++) {
            float a[TM], b[TN];
#pragma unroll
            for (int i4 = 0; i4 < TM / 4; i4++)
                *(float4*)&a[i4 * 4] = *(const float4*)&Xs[kk][ty * TM + i4 * 4];
#pragma unroll
            for (int j4 = 0; j4 < TN / 4; j4++)
                *(float4*)&b[j4 * 4] = *(const float4*)&Ws[kk][tx * TN + j4 * 4];
#pragma unroll
            for (int i = 0; i < TM; i++)
#pragma unroll
                for (int j = 0; j < TN; j++) acc[i][j] += a[i] * b[j];
        }
        __syncthreads();
    }

#pragma unroll
    for (int i = 0; i < TM; i++) {
        int r = row0 + ty * TM + i;
        if (r < M) {
            float dv = g_dinv[r];
#pragma unroll
            for (int j4 = 0; j4 < TN / 4; j4++) {
                float4 v;
                v.x = acc[i][j4 * 4 + 0] * dv;
                v.y = acc[i][j4 * 4 + 1] * dv;
                v.z = acc[i][j4 * 4 + 2] * dv;
                v.w = acc[i][j4 * 4 + 3] * dv;
                size_t idx = (size_t)r * BN + tx * TN + j4 * 4;
                *(float4*)&hs[idx]  = v;
                *(float4*)&ini[idx] = v;
            }
        }
    }
}

// ---------------- v1 GEMM kept for the irregular 64->40 layer ----------------
template<int BM, int BN, int BK, int TM, int TN>
__global__ void gemm_scale_k(const float* __restrict__ X, const float* __restrict__ W,
                             float* __restrict__ hs, float* __restrict__ ini,
                             int M, int K) {
    __shared__ float Xs[BM][BK + 1];
    __shared__ float Ws[BK][BN];
    constexpr int NT = (BM / TM) * (BN / TN);
    const int tid = threadIdx.x;
    const int tx  = tid % (BN / TN);
    const int ty  = tid / (BN / TN);
    const int row0 = blockIdx.x * BM;

    float acc[TM][TN];
#pragma unroll
    for (int i = 0; i < TM; i++)
#pragma unroll
        for (int j = 0; j < TN; j++) acc[i][j] = 0.f;

    for (int k0 = 0; k0 < K; k0 += BK) {
        for (int i = tid; i < BM * BK; i += NT) {
            int r = i / BK, kk = i % BK;
            int gr = row0 + r; if (gr >= M) gr = M - 1;
            int gk = k0 + kk;
            Xs[r][kk] = (gk < K) ? X[(size_t)gr * K + gk] : 0.f;
        }
        for (int i = tid; i < BK * BN; i += NT) {
            int kk = i / BN, c = i % BN;
            int gk = k0 + kk;
            Ws[kk][c] = (gk < K) ? W[(size_t)gk * BN + c] : 0.f;
        }
        __syncthreads();
#pragma unroll
        for (int kk = 0; kk < BK; kk++) {
            float a[TM], b[TN];
#pragma unroll
            for (int i = 0; i < TM; i++) a[i] = Xs[ty * TM + i][kk];
#pragma unroll
            for (int j = 0; j < TN; j++) b[j] = Ws[kk][tx * TN + j];
#pragma unroll
            for (int i = 0; i < TM; i++)
#pragma unroll
                for (int j = 0; j < TN; j++) acc[i][j] += a[i] * b[j];
        }
        __syncthreads();
    }

#pragma unroll
    for (int i = 0; i < TM; i++) {
        int r = row0 + ty * TM + i;
        if (r < M) {
            float dv = g_dinv[r];
#pragma unroll
            for (int j = 0; j < TN; j++) {
                float v = acc[i][j] * dv;
                size_t idx = (size_t)r * BN + tx * TN + j;
                hs[idx]  = v;
                ini[idx] = v;
            }
        }
    }
}

// ---------------- edge scatter-add with vector red ----------------
__device__ __forceinline__ void red_add_v4(float* p, float4 v) {
    asm volatile("red.global.add.v4.f32 [%0], {%1, %2, %3, %4};"
                 :: "l"(p), "f"(v.x), "f"(v.y), "f"(v.z), "f"(v.w) : "memory");
}

template<int C, int EB>
__global__ void scatter_k(const int* __restrict__ src, const int* __restrict__ dst,
                          const float* __restrict__ hs, float* __restrict__ agg, int E) {
    constexpr int CH = C / 4;
    int e = blockIdx.x * EB + threadIdx.y;
    if (e >= E) return;
    int s = src[e];
    int d = dst[e];
    int c = threadIdx.x;
    float4 v = reinterpret_cast<const float4*>(hs)[(size_t)s * CH + c];
    red_add_v4(agg + (size_t)d * C + c * 4, v);
}

// ---------------- finalize: out = [relu](agg*dinv + b) ----------------
template<bool RELU, int C>
__global__ void finalize_k(const float* __restrict__ agg, const float* __restrict__ b,
                           float* __restrict__ out, int n) {
    int i = blockIdx.x * blockDim.x + threadIdx.x;
    if (i >= n * C) return;
    int r = i / C, c = i % C;
    float v = agg[i] * g_dinv[r] + b[c];
    if (RELU) v = fmaxf(v, 0.f);
    out[i] = v;
}

// ---------------- final layer: bias + log_softmax (40 cols, one warp/row) ----
__global__ void lsm_k(const float* __restrict__ agg, const float* __restrict__ b,
                      float* __restrict__ out, int n) {
    int gid  = blockIdx.x * blockDim.x + threadIdx.x;
    int row  = gid >> 5;
    int lane = threadIdx.x & 31;
    if (row >= n) return;
    float dv = g_dinv[row];
    const float* rp = agg + (size_t)row * F3;
    float v0 = rp[lane] * dv + b[lane];
    float v1 = (lane < F3 - 32) ? rp[lane + 32] * dv + b[lane + 32] : -INFINITY;
    float m = fmaxf(v0, v1);
#pragma unroll
    for (int o = 16; o; o >>= 1) m = fmaxf(m, __shfl_xor_sync(0xffffffffu, m, o));
    float s = expf(v0 - m) + ((lane < F3 - 32) ? expf(v1 - m) : 0.f);
#pragma unroll
    for (int o = 16; o; o >>= 1) s += __shfl_xor_sync(0xffffffffu, s, o);
    float lse = logf(s) + m;
    float* op = out + (size_t)row * F3;
    op[lane] = v0 - lse;
    if (lane < F3 - 32) op[lane + 32] = v1 - lse;
}

extern "C" void kernel_launch(void* const* d_in, const int* in_sizes, int n_in,
                              void* d_out, int out_size) {
    const float* x   = (const float*)d_in[0];
    const int*   ei  = (const int*)d_in[1];     // int32 (JAX x64 disabled)
    const float* W1  = (const float*)d_in[2];
    const float* b1  = (const float*)d_in[3];
    const float* W2  = (const float*)d_in[4];
    const float* b2  = (const float*)d_in[5];
    const float* W4  = (const float*)d_in[6];
    const float* b4  = (const float*)d_in[7];
    float* out = (float*)d_out;

    const int N = in_sizes[0] / F0;       // 100000
    const int E = in_sizes[1] / 2;        // 1600000
    const int* src = ei;
    const int* dst = ei + E;

    float *A, *B, *C;
    cudaGetSymbolAddress((void**)&A, g_bufA);
    cudaGetSymbolAddress((void**)&B, g_bufB);
    cudaGetSymbolAddress((void**)&C, g_bufC);

    // degrees
    deg_init_k <<<(N + 255) / 256, 256>>>(N);
    deg_count_k<<<(E + 255) / 256, 256>>>(dst, E);
    dinv_k     <<<(N + 255) / 256, 256>>>(N);

    // ---- layer 1: 500 -> 128 (tf32 tensor cores) ----
    gemm_tf32_k<<<(N + 127) / 128, 256>>>(x, W1, A, B, N, F0);
    scatter_k<128, 8><<<(E + 7) / 8, dim3(32, 8)>>>(src, dst, A, B, E);
    finalize_k<true, 128><<<((size_t)N * 128 + 255) / 256, 256>>>(B, b1, A, N);

    // ---- layer 2: 128 -> 64 ----
    gemm_v2_k<128, 64, 16, 8, 4><<<(N + 127) / 128, 256>>>(A, W2, B, C, N, F1);
    scatter_k<64, 16><<<(E + 15) / 16, dim3(16, 16)>>>(src, dst, B, C, E);
    finalize_k<true, 64><<<((size_t)N * 64 + 255) / 256, 256>>>(C, b2, A, N);

    // ---- layer 3: 64 -> 40 + log_softmax ----
    gemm_scale_k<128, 40, 16, 8, 5><<<(N + 127) / 128, 128>>>(A, W4, B, C, N, F2);
    scatter_k<40, 16><<<(E + 15) / 16, dim3(10, 16)>>>(src, dst, B, C, E);
    lsm_k<<<(N * 32 + 255) / 256, 256>>>(C, b4, out, N);
}

// round 5
// speedup vs baseline: 3.6428x; 1.6536x over previous
#include <cuda_runtime.h>
#include <math.h>

#define NN 100000
#define NE 1600000
#define F0 500
#define F1 128
#define F2 64
#define F3 40
#define SCAN_B 1024
#define NBLK ((NN + SCAN_B - 1) / SCAN_B)

// Static scratch (allocation-free rule: __device__ globals)
__device__ int   g_cnt [NN];          // in-edge count (no self-loop)
__device__ int   g_off [NN];          // CSR row offsets (exclusive scan of cnt)
__device__ int   g_cur [NN];          // fill cursors
__device__ int   g_bsum[SCAN_B];      // block sums for scan
__device__ int   g_csr [NE];          // src indices sorted by dst
__device__ float g_dinv[NN];
__device__ __align__(16) float g_bufA[(size_t)NN * F1];
__device__ __align__(16) float g_bufB[(size_t)NN * F1];
__device__ __align__(16) float g_bufC[(size_t)NN * F1];

// ---------------- degree / CSR build ----------------
__global__ void cnt_init_k(int n) {
    int i = blockIdx.x * blockDim.x + threadIdx.x;
    if (i < n) g_cnt[i] = 0;
}
__global__ void cnt_count_k(const int* __restrict__ dst, int e) {
    int i = blockIdx.x * blockDim.x + threadIdx.x;
    if (i < e) atomicAdd(&g_cnt[dst[i]], 1);
}
__global__ void dinv_k(int n) {
    int i = blockIdx.x * blockDim.x + threadIdx.x;
    if (i < n) g_dinv[i] = rsqrtf((float)(g_cnt[i] + 1));   // +1 self-loop
}
// per-block exclusive scan of g_cnt -> g_off, block totals -> g_bsum
__global__ void scan1_k(int n) {
    __shared__ int sh[SCAN_B];
    int t = threadIdx.x, g = blockIdx.x * SCAN_B + t;
    int v = (g < n) ? g_cnt[g] : 0;
    sh[t] = v; __syncthreads();
#pragma unroll
    for (int o = 1; o < SCAN_B; o <<= 1) {
        int x = (t >= o) ? sh[t - o] : 0;
        __syncthreads();
        sh[t] += x;
        __syncthreads();
    }
    if (g < n) g_off[g] = sh[t] - v;          // exclusive
    if (t == SCAN_B - 1) g_bsum[blockIdx.x] = sh[t];
}
// single-block exclusive scan of g_bsum
__global__ void scan2_k(int nb) {
    __shared__ int sh[SCAN_B];
    int t = threadIdx.x;
    int v = (t < nb) ? g_bsum[t] : 0;
    sh[t] = v; __syncthreads();
#pragma unroll
    for (int o = 1; o < SCAN_B; o <<= 1) {
        int x = (t >= o) ? sh[t - o] : 0;
        __syncthreads();
        sh[t] += x;
        __syncthreads();
    }
    if (t < nb) g_bsum[t] = sh[t] - v;        // exclusive
}
__global__ void scan3_k(int n) {
    int i = blockIdx.x * blockDim.x + threadIdx.x;
    if (i < n) {
        int o = g_off[i] + g_bsum[i / SCAN_B];
        g_off[i] = o;
        g_cur[i] = o;
    }
}
__global__ void csr_fill_k(const int* __restrict__ src, const int* __restrict__ dst, int e) {
    int i = blockIdx.x * blockDim.x + threadIdx.x;
    if (i < e) {
        int pos = atomicAdd(&g_cur[dst[i]], 1);
        g_csr[pos] = src[i];
    }
}

// ---------------- tf32 tensor-core GEMM (layer 1) ----------------
__device__ __forceinline__ unsigned f2tf32(float x) {
    unsigned r;
    asm("cvt.rna.tf32.f32 %0, %1;" : "=r"(r) : "f"(x));
    return r;
}
__device__ __forceinline__ void mma_tf32(float* d, const unsigned* a, const unsigned* b) {
    asm volatile(
        "mma.sync.aligned.m16n8k8.row.col.f32.tf32.tf32.f32 "
        "{%0,%1,%2,%3},{%4,%5,%6,%7},{%8,%9},{%0,%1,%2,%3};"
        : "+f"(d[0]), "+f"(d[1]), "+f"(d[2]), "+f"(d[3])
        : "r"(a[0]), "r"(a[1]), "r"(a[2]), "r"(a[3]), "r"(b[0]), "r"(b[1]));
}

// BM=128, BN=128, BK=32, 256 threads, warp tile 32x64.
// hs[r,c] = (X[r,:] @ W[:,c]) * dinv[r]
__global__ void __launch_bounds__(256) gemm_tf32_k(
        const float* __restrict__ X, const float* __restrict__ W,
        float* __restrict__ hs, int M, int K) {
    constexpr int BM = 128, BN = 128, BK = 32;
    constexpr int BKP = BK + 1;
    constexpr int BNP = BN + 4;
    __shared__ unsigned Xs[BM][BKP];
    __shared__ unsigned Ws[BK][BNP];

    const int tid    = threadIdx.x;
    const int lane   = tid & 31;
    const int wid    = tid >> 5;
    const int warp_m = wid & 3;
    const int warp_n = wid >> 2;
    const int row0   = blockIdx.x * BM;
    const int lq     = lane >> 2;
    const int lr     = lane & 3;

    float acc[2][8][4];
#pragma unroll
    for (int i = 0; i < 2; i++)
#pragma unroll
        for (int j = 0; j < 8; j++)
#pragma unroll
            for (int t = 0; t < 4; t++) acc[i][j][t] = 0.f;

    const int nchunk = (K + BK - 1) / BK;
    for (int kc = 0; kc < nchunk; kc++) {
        const int k0 = kc * BK;
        if (k0 + BK <= K) {
#pragma unroll
            for (int it = 0; it < 4; it++) {
                int idx = tid + it * 256;
                int r   = idx >> 3;
                int kv  = idx & 7;
                int gr  = row0 + r; if (gr >= M) gr = M - 1;
                float4 v = *(const float4*)&X[(size_t)gr * K + k0 + kv * 4];
                Xs[r][kv * 4 + 0] = f2tf32(v.x);
                Xs[r][kv * 4 + 1] = f2tf32(v.y);
                Xs[r][kv * 4 + 2] = f2tf32(v.z);
                Xs[r][kv * 4 + 3] = f2tf32(v.w);
            }
        } else {
            for (int idx = tid; idx < BM * BK; idx += 256) {
                int r = idx >> 5, kk = idx & 31;
                int gr = row0 + r; if (gr >= M) gr = M - 1;
                int gk = k0 + kk;
                Xs[r][kk] = (gk < K) ? f2tf32(X[(size_t)gr * K + gk]) : 0u;
            }
        }
#pragma unroll
        for (int it = 0; it < 4; it++) {
            int idx = tid + it * 256;
            int kk  = idx >> 5;
            int cv  = idx & 31;
            int gk  = k0 + kk;
            float4 v = (gk < K) ? *(const float4*)&W[(size_t)gk * BN + cv * 4]
                                : make_float4(0.f, 0.f, 0.f, 0.f);
            Ws[kk][cv * 4 + 0] = f2tf32(v.x);
            Ws[kk][cv * 4 + 1] = f2tf32(v.y);
            Ws[kk][cv * 4 + 2] = f2tf32(v.z);
            Ws[kk][cv * 4 + 3] = f2tf32(v.w);
        }
        __syncthreads();

#pragma unroll
        for (int ks = 0; ks < 4; ks++) {
            const int kb = ks * 8;
            unsigned a[2][4], b[8][2];
#pragma unroll
            for (int i = 0; i < 2; i++) {
                int r = warp_m * 32 + i * 16;
                a[i][0] = Xs[r + lq    ][kb + lr    ];
                a[i][1] = Xs[r + lq + 8][kb + lr    ];
                a[i][2] = Xs[r + lq    ][kb + lr + 4];
                a[i][3] = Xs[r + lq + 8][kb + lr + 4];
            }
#pragma unroll
            for (int j = 0; j < 8; j++) {
                int n = warp_n * 64 + j * 8 + lq;
                b[j][0] = Ws[kb + lr    ][n];
                b[j][1] = Ws[kb + lr + 4][n];
            }
#pragma unroll
            for (int i = 0; i < 2; i++)
#pragma unroll
                for (int j = 0; j < 8; j++) mma_tf32(acc[i][j], a[i], b[j]);
        }
        __syncthreads();
    }

#pragma unroll
    for (int i = 0; i < 2; i++) {
        int r_lo = row0 + warp_m * 32 + i * 16 + lq;
        int r_hi = r_lo + 8;
        float dv_lo = (r_lo < M) ? g_dinv[r_lo] : 0.f;
        float dv_hi = (r_hi < M) ? g_dinv[r_hi] : 0.f;
#pragma unroll
        for (int j = 0; j < 8; j++) {
            int c = warp_n * 64 + j * 8 + lr * 2;
            if (r_lo < M)
                *(float2*)&hs[(size_t)r_lo * BN + c] =
                    make_float2(acc[i][j][0] * dv_lo, acc[i][j][1] * dv_lo);
            if (r_hi < M)
                *(float2*)&hs[(size_t)r_hi * BN + c] =
                    make_float2(acc[i][j][2] * dv_hi, acc[i][j][3] * dv_hi);
        }
    }
}

// ---------------- v2 FFMA GEMM (layer 2) ----------------
template<int BM, int BN, int BK, int TM, int TN>
__global__ void gemm_v2_k(const float* __restrict__ X, const float* __restrict__ W,
                          float* __restrict__ hs, int M, int K) {
    constexpr int NT  = (BM / TM) * (BN / TN);
    constexpr int BMP = BM + 4;
    __shared__ float Xs[BK][BMP];
    __shared__ float Ws[BK][BN];

    const int tid  = threadIdx.x;
    const int tx   = tid % (BN / TN);
    const int ty   = tid / (BN / TN);
    const int row0 = blockIdx.x * BM;

    float acc[TM][TN];
#pragma unroll
    for (int i = 0; i < TM; i++)
#pragma unroll
        for (int j = 0; j < TN; j++) acc[i][j] = 0.f;

    for (int k0 = 0; k0 < K; k0 += BK) {
#pragma unroll
        for (int idx = tid; idx < BM * BK / 4; idx += NT) {
            int r  = idx / (BK / 4);
            int kv = idx % (BK / 4);
            int gr = row0 + r; if (gr >= M) gr = M - 1;
            float4 v = *(const float4*)&X[(size_t)gr * K + k0 + kv * 4];
            Xs[kv * 4 + 0][r] = v.x;
            Xs[kv * 4 + 1][r] = v.y;
            Xs[kv * 4 + 2][r] = v.z;
            Xs[kv * 4 + 3][r] = v.w;
        }
#pragma unroll
        for (int idx = tid; idx < BK * BN / 4; idx += NT) {
            int kk = idx / (BN / 4);
            int cv = idx % (BN / 4);
            float4 v = *(const float4*)&W[(size_t)(k0 + kk) * BN + cv * 4];
            *(float4*)&Ws[kk][cv * 4] = v;
        }
        __syncthreads();

#pragma unroll
        for (int kk = 0; kk < BK; kk++) {
            float a[TM], b[TN];
#pragma unroll
            for (int i4 = 0; i4 < TM / 4; i4++)
                *(float4*)&a[i4 * 4] = *(const float4*)&Xs[kk][ty * TM + i4 * 4];
#pragma unroll
            for (int j4 = 0; j4 < TN / 4; j4++)
                *(float4*)&b[j4 * 4] = *(const float4*)&Ws[kk][tx * TN + j4 * 4];
#pragma unroll
            for (int i = 0; i < TM; i++)
#pragma unroll
                for (int j = 0; j < TN; j++) acc[i][j] += a[i] * b[j];
        }
        __syncthreads();
    }

#pragma unroll
    for (int i = 0; i < TM; i++) {
        int r = row0 + ty * TM + i;
        if (r < M) {
            float dv = g_dinv[r];
#pragma unroll
            for (int j4 = 0; j4 < TN / 4; j4++) {
                float4 v;
                v.x = acc[i][j4 * 4 + 0] * dv;
                v.y = acc[i][j4 * 4 + 1] * dv;
                v.z = acc[i][j4 * 4 + 2] * dv;
                v.w = acc[i][j4 * 4 + 3] * dv;
                *(float4*)&hs[(size_t)r * BN + tx * TN + j4 * 4] = v;
            }
        }
    }
}

// ---------------- v1 GEMM for the irregular 64->40 layer ----------------
template<int BM, int BN, int BK, int TM, int TN>
__global__ void gemm_scale_k(const float* __restrict__ X, const float* __restrict__ W,
                             float* __restrict__ hs, int M, int K) {
    __shared__ float Xs[BM][BK + 1];
    __shared__ float Ws[BK][BN];
    constexpr int NT = (BM / TM) * (BN / TN);
    const int tid = threadIdx.x;
    const int tx  = tid % (BN / TN);
    const int ty  = tid / (BN / TN);
    const int row0 = blockIdx.x * BM;

    float acc[TM][TN];
#pragma unroll
    for (int i = 0; i < TM; i++)
#pragma unroll
        for (int j = 0; j < TN; j++) acc[i][j] = 0.f;

    for (int k0 = 0; k0 < K; k0 += BK) {
        for (int i = tid; i < BM * BK; i += NT) {
            int r = i / BK, kk = i % BK;
            int gr = row0 + r; if (gr >= M) gr = M - 1;
            int gk = k0 + kk;
            Xs[r][kk] = (gk < K) ? X[(size_t)gr * K + gk] : 0.f;
        }
        for (int i = tid; i < BK * BN; i += NT) {
            int kk = i / BN, c = i % BN;
            int gk = k0 + kk;
            Ws[kk][c] = (gk < K) ? W[(size_t)gk * BN + c] : 0.f;
        }
        __syncthreads();
#pragma unroll
        for (int kk = 0; kk < BK; kk++) {
            float a[TM], b[TN];
#pragma unroll
            for (int i = 0; i < TM; i++) a[i] = Xs[ty * TM + i][kk];
#pragma unroll
            for (int j = 0; j < TN; j++) b[j] = Ws[kk][tx * TN + j];
#pragma unroll
            for (int i = 0; i < TM; i++)
#pragma unroll
                for (int j = 0; j < TN; j++) acc[i][j] += a[i] * b[j];
        }
        __syncthreads();
    }

#pragma unroll
    for (int i = 0; i < TM; i++) {
        int r = row0 + ty * TM + i;
        if (r < M) {
            float dv = g_dinv[r];
#pragma unroll
            for (int j = 0; j < TN; j++)
                hs[(size_t)r * BN + tx * TN + j] = acc[i][j] * dv;
        }
    }
}

// ---------------- pull aggregation (fused scatter+finalize, no atomics) ----
// thread (node, c): acc = hs[node] (self) + sum over in-edges hs[src];
// EPI=1: out = relu(acc*dinv + b);  EPI=0: out = acc (raw, for log_softmax).
template<int C, int EPI>
__global__ void pull_k(const float* __restrict__ hs, const float* __restrict__ bias,
                       float* __restrict__ out, int n) {
    constexpr int CH = C / 4;
    int t = blockIdx.x * blockDim.x + threadIdx.x;
    int node = t / CH;
    int c    = t % CH;
    if (node >= n) return;

    const float4* hs4 = (const float4*)hs;
    float4 acc = hs4[(size_t)node * CH + c];              // self-loop
    int beg = g_off[node];
    int cnt = g_cnt[node];
    for (int i = 0; i < cnt; i++) {
        int s = g_csr[beg + i];
        float4 v = hs4[(size_t)s * CH + c];
        acc.x += v.x; acc.y += v.y; acc.z += v.z; acc.w += v.w;
    }
    if (EPI) {
        float dv = g_dinv[node];
        float4 b = ((const float4*)bias)[c];
        acc.x = fmaxf(acc.x * dv + b.x, 0.f);
        acc.y = fmaxf(acc.y * dv + b.y, 0.f);
        acc.z = fmaxf(acc.z * dv + b.z, 0.f);
        acc.w = fmaxf(acc.w * dv + b.w, 0.f);
    }
    ((float4*)out)[(size_t)node * CH + c] = acc;
}

// ---------------- final layer: dinv + bias + log_softmax ----------------
__global__ void lsm_k(const float* __restrict__ agg, const float* __restrict__ b,
                      float* __restrict__ out, int n) {
    int gid  = blockIdx.x * blockDim.x + threadIdx.x;
    int row  = gid >> 5;
    int lane = threadIdx.x & 31;
    if (row >= n) return;
    float dv = g_dinv[row];
    const float* rp = agg + (size_t)row * F3;
    float v0 = rp[lane] * dv + b[lane];
    float v1 = (lane < F3 - 32) ? rp[lane + 32] * dv + b[lane + 32] : -INFINITY;
    float m = fmaxf(v0, v1);
#pragma unroll
    for (int o = 16; o; o >>= 1) m = fmaxf(m, __shfl_xor_sync(0xffffffffu, m, o));
    float s = expf(v0 - m) + ((lane < F3 - 32) ? expf(v1 - m) : 0.f);
#pragma unroll
    for (int o = 16; o; o >>= 1) s += __shfl_xor_sync(0xffffffffu, s, o);
    float lse = logf(s) + m;
    float* op = out + (size_t)row * F3;
    op[lane] = v0 - lse;
    if (lane < F3 - 32) op[lane + 32] = v1 - lse;
}

extern "C" void kernel_launch(void* const* d_in, const int* in_sizes, int n_in,
                              void* d_out, int out_size) {
    const float* x   = (const float*)d_in[0];
    const int*   ei  = (const int*)d_in[1];     // int32 (JAX x64 disabled)
    const float* W1  = (const float*)d_in[2];
    const float* b1  = (const float*)d_in[3];
    const float* W2  = (const float*)d_in[4];
    const float* b2  = (const float*)d_in[5];
    const float* W4  = (const float*)d_in[6];
    const float* b4  = (const float*)d_in[7];
    float* out = (float*)d_out;

    const int N = in_sizes[0] / F0;       // 100000
    const int E = in_sizes[1] / 2;        // 1600000
    const int* src = ei;
    const int* dst = ei + E;

    float *A, *B, *C;
    cudaGetSymbolAddress((void**)&A, g_bufA);
    cudaGetSymbolAddress((void**)&B, g_bufB);
    cudaGetSymbolAddress((void**)&C, g_bufC);

    // ---- CSR build + dinv ----
    cnt_init_k <<<(N + 255) / 256, 256>>>(N);
    cnt_count_k<<<(E + 255) / 256, 256>>>(dst, E);
    dinv_k     <<<(N + 255) / 256, 256>>>(N);
    scan1_k    <<<NBLK, SCAN_B>>>(N);
    scan2_k    <<<1, SCAN_B>>>(NBLK);
    scan3_k    <<<(N + 255) / 256, 256>>>(N);
    csr_fill_k <<<(E + 255) / 256, 256>>>(src, dst, E);

    // ---- layer 1: 500 -> 128 (tf32 tensor cores) ----
    gemm_tf32_k<<<(N + 127) / 128, 256>>>(x, W1, A, N, F0);
    pull_k<128, 1><<<((size_t)N * 32 + 255) / 256, 256>>>(A, b1, B, N);

    // ---- layer 2: 128 -> 64 ----
    gemm_v2_k<128, 64, 16, 8, 4><<<(N + 127) / 128, 256>>>(B, W2, A, N, F1);
    pull_k<64, 1><<<((size_t)N * 16 + 255) / 256, 256>>>(A, b2, B, N);

    // ---- layer 3: 64 -> 40 + log_softmax ----
    gemm_scale_k<128, 40, 16, 8, 5><<<(N + 127) / 128, 128>>>(B, W4, C, N, F2);
    pull_k<40, 0><<<((size_t)N * 10 + 255) / 256, 256>>>(C, (const float*)0, A, N);
    lsm_k<<<(N * 32 + 255) / 256, 256>>>(A, b4, out, N);
}

// round 6
// speedup vs baseline: 4.4057x; 1.2094x over previous
#include <cuda_runtime.h>
#include <math.h>

#define NN 100000
#define NE 1600000
#define F0 500
#define F1 128
#define F2 64
#define F3 40
#define SCAN_B 1024
#define NBLK ((NN + SCAN_B - 1) / SCAN_B)

// Static scratch (allocation-free rule: __device__ globals)
__device__ int   g_cnt [NN];          // in-edge count (no self-loop)
__device__ int   g_off [NN];          // CSR row offsets
__device__ int   g_cur [NN];          // fill cursors
__device__ int   g_bsum[SCAN_B];
__device__ int   g_csr [NE];          // src indices grouped by dst
__device__ float g_dinv[NN];
__device__ __align__(16) float g_bufA[(size_t)NN * F1];
__device__ __align__(16) float g_bufB[(size_t)NN * F1];
__device__ __align__(16) float g_bufC[(size_t)NN * F1];

// ---------------- degree / CSR build ----------------
__global__ void cnt_init_k(int n) {
    int i = blockIdx.x * blockDim.x + threadIdx.x;
    if (i < n) g_cnt[i] = 0;
}
__global__ void cnt_count_k(const int* __restrict__ dst, int e) {
    int i = blockIdx.x * blockDim.x + threadIdx.x;
    if (i < e) atomicAdd(&g_cnt[dst[i]], 1);
}
__global__ void dinv_k(int n) {
    int i = blockIdx.x * blockDim.x + threadIdx.x;
    if (i < n) g_dinv[i] = rsqrtf((float)(g_cnt[i] + 1));   // +1 self-loop
}
__global__ void scan1_k(int n) {
    __shared__ int sh[SCAN_B];
    int t = threadIdx.x, g = blockIdx.x * SCAN_B + t;
    int v = (g < n) ? g_cnt[g] : 0;
    sh[t] = v; __syncthreads();
#pragma unroll
    for (int o = 1; o < SCAN_B; o <<= 1) {
        int x = (t >= o) ? sh[t - o] : 0;
        __syncthreads();
        sh[t] += x;
        __syncthreads();
    }
    if (g < n) g_off[g] = sh[t] - v;
    if (t == SCAN_B - 1) g_bsum[blockIdx.x] = sh[t];
}
__global__ void scan2_k(int nb) {
    __shared__ int sh[SCAN_B];
    int t = threadIdx.x;
    int v = (t < nb) ? g_bsum[t] : 0;
    sh[t] = v; __syncthreads();
#pragma unroll
    for (int o = 1; o < SCAN_B; o <<= 1) {
        int x = (t >= o) ? sh[t - o] : 0;
        __syncthreads();
        sh[t] += x;
        __syncthreads();
    }
    if (t < nb) g_bsum[t] = sh[t] - v;
}
__global__ void scan3_k(int n) {
    int i = blockIdx.x * blockDim.x + threadIdx.x;
    if (i < n) {
        int o = g_off[i] + g_bsum[i / SCAN_B];
        g_off[i] = o;
        g_cur[i] = o;
    }
}
__global__ void csr_fill_k(const int* __restrict__ src, const int* __restrict__ dst, int e) {
    int i = blockIdx.x * blockDim.x + threadIdx.x;
    if (i < e) {
        int pos = atomicAdd(&g_cur[dst[i]], 1);
        g_csr[pos] = src[i];
    }
}

// ---------------- tf32 helpers ----------------
__device__ __forceinline__ unsigned f2tf32(float x) {
    unsigned r;
    asm("cvt.rna.tf32.f32 %0, %1;" : "=r"(r) : "f"(x));
    return r;
}
__device__ __forceinline__ void mma_tf32(float* d, const unsigned* a, const unsigned* b) {
    asm volatile(
        "mma.sync.aligned.m16n8k8.row.col.f32.tf32.tf32.f32 "
        "{%0,%1,%2,%3},{%4,%5,%6,%7},{%8,%9},{%0,%1,%2,%3};"
        : "+f"(d[0]), "+f"(d[1]), "+f"(d[2]), "+f"(d[3])
        : "r"(a[0]), "r"(a[1]), "r"(a[2]), "r"(a[3]), "r"(b[0]), "r"(b[1]));
}
__device__ __forceinline__ void cp16(float* s, const float* g, bool pred) {
    unsigned sa = (unsigned)__cvta_generic_to_shared(s);
    int bytes = pred ? 16 : 0;      // src-size 0 => zero-fill 16B
    asm volatile("cp.async.ca.shared.global [%0], [%1], 16, %2;"
                 :: "r"(sa), "l"(g), "r"(bytes));
}
#define CP_COMMIT() asm volatile("cp.async.commit_group;" ::: "memory")
#define CP_WAIT(N)  asm volatile("cp.async.wait_group %0;" :: "n"(N) : "memory")

// ---------------- pipelined tf32 tensor-core GEMM ----------------
// BM=128, BK=32, 256 threads (8 warps). BN in {128, 64}.
// Warp tile: 32 x (BN/2).  hs[r,c] = (X[r,:] @ W[:,c]) * dinv[r]
template<int BN>
__global__ void __launch_bounds__(256) gemm_tf32_pipe_k(
        const float* __restrict__ X, const float* __restrict__ W,
        float* __restrict__ hs, int M, int K) {
    constexpr int BM = 128, BK = 32;
    constexpr int XSTR = BK + 4;                 // 36 floats (16B-aligned rows)
    constexpr int WSTR = BN + 4;
    constexpr int NJ = BN / 16;                  // mma n-tiles per warp
    constexpr int XSZ = BM * XSTR;
    constexpr int WSZ = BK * WSTR;

    extern __shared__ float smem[];
    float* Xs0 = smem;                           // [2][XSZ]
    float* Ws0 = smem + 2 * XSZ;                 // [2][WSZ]

    const int tid    = threadIdx.x;
    const int lane   = tid & 31;
    const int wid    = tid >> 5;
    const int warp_m = wid & 3;
    const int warp_n = wid >> 2;
    const int row0   = blockIdx.x * BM;
    const int lq     = lane >> 2;
    const int lr     = lane & 3;

    float acc[2][NJ][4];
#pragma unroll
    for (int i = 0; i < 2; i++)
#pragma unroll
        for (int j = 0; j < NJ; j++)
#pragma unroll
            for (int t = 0; t < 4; t++) acc[i][j][t] = 0.f;

    const int nchunk = (K + BK - 1) / BK;

    // tile loader: stage s <- chunk at k0
    auto load_tile = [&](int s, int k0) {
        float* Xs = Xs0 + s * XSZ;
        float* Ws = Ws0 + s * WSZ;
#pragma unroll
        for (int it = 0; it < 4; it++) {          // A: 128x32 = 1024 float4
            int idx = tid + it * 256;
            int r   = idx >> 3;
            int kv  = idx & 7;
            int gr  = row0 + r; if (gr >= M) gr = M - 1;
            bool p  = (k0 + kv * 4 + 4 <= K);
            int gk  = p ? (k0 + kv * 4) : 0;
            cp16(&Xs[r * XSTR + kv * 4], &X[(size_t)gr * K + gk], p);
        }
        constexpr int BIT = (BK * BN / 4) / 256;  // B float4 slots / 256
#pragma unroll
        for (int it = 0; it < BIT; it++) {
            int idx = tid + it * 256;
            int kk  = idx / (BN / 4);
            int cv  = idx % (BN / 4);
            bool p  = (k0 + kk < K);
            int gk  = p ? (k0 + kk) : 0;
            cp16(&Ws[kk * WSTR + cv * 4], &W[(size_t)gk * BN + cv * 4], p);
        }
    };

    load_tile(0, 0);
    CP_COMMIT();

    for (int kc = 0; kc < nchunk; kc++) {
        const int s = kc & 1;
        if (kc + 1 < nchunk) {
            load_tile(s ^ 1, (kc + 1) * BK);
            CP_COMMIT();
            CP_WAIT(1);
        } else {
            CP_WAIT(0);
        }
        __syncthreads();

        const float* Xs = Xs0 + s * XSZ;
        const float* Ws = Ws0 + s * WSZ;
#pragma unroll
        for (int ks = 0; ks < 4; ks++) {
            const int kb = ks * 8;
            unsigned a[2][4], b[NJ][2];
#pragma unroll
            for (int i = 0; i < 2; i++) {
                int r = warp_m * 32 + i * 16;
                a[i][0] = f2tf32(Xs[(r + lq    ) * XSTR + kb + lr    ]);
                a[i][1] = f2tf32(Xs[(r + lq + 8) * XSTR + kb + lr    ]);
                a[i][2] = f2tf32(Xs[(r + lq    ) * XSTR + kb + lr + 4]);
                a[i][3] = f2tf32(Xs[(r + lq + 8) * XSTR + kb + lr + 4]);
            }
#pragma unroll
            for (int j = 0; j < NJ; j++) {
                int n = warp_n * (BN / 2) + j * 8 + lq;
                b[j][0] = f2tf32(Ws[(kb + lr    ) * WSTR + n]);
                b[j][1] = f2tf32(Ws[(kb + lr + 4) * WSTR + n]);
            }
#pragma unroll
            for (int i = 0; i < 2; i++)
#pragma unroll
                for (int j = 0; j < NJ; j++) mma_tf32(acc[i][j], a[i], b[j]);
        }
        __syncthreads();
    }

    // epilogue: scale by dinv[row]
#pragma unroll
    for (int i = 0; i < 2; i++) {
        int r_lo = row0 + warp_m * 32 + i * 16 + lq;
        int r_hi = r_lo + 8;
        float dv_lo = (r_lo < M) ? g_dinv[r_lo] : 0.f;
        float dv_hi = (r_hi < M) ? g_dinv[r_hi] : 0.f;
#pragma unroll
        for (int j = 0; j < NJ; j++) {
            int c = warp_n * (BN / 2) + j * 8 + lr * 2;
            if (r_lo < M)
                *(float2*)&hs[(size_t)r_lo * BN + c] =
                    make_float2(acc[i][j][0] * dv_lo, acc[i][j][1] * dv_lo);
            if (r_hi < M)
                *(float2*)&hs[(size_t)r_hi * BN + c] =
                    make_float2(acc[i][j][2] * dv_hi, acc[i][j][3] * dv_hi);
        }
    }
}

// ---------------- fp32 GEMM for the small 64->40 layer ----------------
template<int BM, int BN, int BK, int TM, int TN>
__global__ void gemm_scale_k(const float* __restrict__ X, const float* __restrict__ W,
                             float* __restrict__ hs, int M, int K) {
    __shared__ float Xs[BM][BK + 1];
    __shared__ float Ws[BK][BN];
    constexpr int NT = (BM / TM) * (BN / TN);
    const int tid = threadIdx.x;
    const int tx  = tid % (BN / TN);
    const int ty  = tid / (BN / TN);
    const int row0 = blockIdx.x * BM;

    float acc[TM][TN];
#pragma unroll
    for (int i = 0; i < TM; i++)
#pragma unroll
        for (int j = 0; j < TN; j++) acc[i][j] = 0.f;

    for (int k0 = 0; k0 < K; k0 += BK) {
        for (int i = tid; i < BM * BK; i += NT) {
            int r = i / BK, kk = i % BK;
            int gr = row0 + r; if (gr >= M) gr = M - 1;
            int gk = k0 + kk;
            Xs[r][kk] = (gk < K) ? X[(size_t)gr * K + gk] : 0.f;
        }
        for (int i = tid; i < BK * BN; i += NT) {
            int kk = i / BN, c = i % BN;
            int gk = k0 + kk;
            Ws[kk][c] = (gk < K) ? W[(size_t)gk * BN + c] : 0.f;
        }
        __syncthreads();
#pragma unroll
        for (int kk = 0; kk < BK; kk++) {
            float a[TM], b[TN];
#pragma unroll
            for (int i = 0; i < TM; i++) a[i] = Xs[ty * TM + i][kk];
#pragma unroll
            for (int j = 0; j < TN; j++) b[j] = Ws[kk][tx * TN + j];
#pragma unroll
            for (int i = 0; i < TM; i++)
#pragma unroll
                for (int j = 0; j < TN; j++) acc[i][j] += a[i] * b[j];
        }
        __syncthreads();
    }

#pragma unroll
    for (int i = 0; i < TM; i++) {
        int r = row0 + ty * TM + i;
        if (r < M) {
            float dv = g_dinv[r];
#pragma unroll
            for (int j = 0; j < TN; j++)
                hs[(size_t)r * BN + tx * TN + j] = acc[i][j] * dv;
        }
    }
}

// ---------------- pull aggregation (fused, no atomics) ----------------
template<int C, int EPI>
__global__ void pull_k(const float* __restrict__ hs, const float* __restrict__ bias,
                       float* __restrict__ out, int n) {
    constexpr int CH = C / 4;
    int t = blockIdx.x * blockDim.x + threadIdx.x;
    int node = t / CH;
    int c    = t % CH;
    if (node >= n) return;

    const float4* hs4 = (const float4*)hs;
    float4 acc = hs4[(size_t)node * CH + c];              // self-loop
    int beg = g_off[node];
    int cnt = g_cnt[node];
    for (int i = 0; i < cnt; i++) {
        int s = g_csr[beg + i];
        float4 v = hs4[(size_t)s * CH + c];
        acc.x += v.x; acc.y += v.y; acc.z += v.z; acc.w += v.w;
    }
    if (EPI) {
        float dv = g_dinv[node];
        float4 b = ((const float4*)bias)[c];
        acc.x = fmaxf(acc.x * dv + b.x, 0.f);
        acc.y = fmaxf(acc.y * dv + b.y, 0.f);
        acc.z = fmaxf(acc.z * dv + b.z, 0.f);
        acc.w = fmaxf(acc.w * dv + b.w, 0.f);
    }
    ((float4*)out)[(size_t)node * CH + c] = acc;
}

// ---------------- final layer: dinv + bias + log_softmax ----------------
__global__ void lsm_k(const float* __restrict__ agg, const float* __restrict__ b,
                      float* __restrict__ out, int n) {
    int gid  = blockIdx.x * blockDim.x + threadIdx.x;
    int row  = gid >> 5;
    int lane = threadIdx.x & 31;
    if (row >= n) return;
    float dv = g_dinv[row];
    const float* rp = agg + (size_t)row * F3;
    float v0 = rp[lane] * dv + b[lane];
    float v1 = (lane < F3 - 32) ? rp[lane + 32] * dv + b[lane + 32] : -INFINITY;
    float m = fmaxf(v0, v1);
#pragma unroll
    for (int o = 16; o; o >>= 1) m = fmaxf(m, __shfl_xor_sync(0xffffffffu, m, o));
    float s = expf(v0 - m) + ((lane < F3 - 32) ? expf(v1 - m) : 0.f);
#pragma unroll
    for (int o = 16; o; o >>= 1) s += __shfl_xor_sync(0xffffffffu, s, o);
    float lse = logf(s) + m;
    float* op = out + (size_t)row * F3;
    op[lane] = v0 - lse;
    if (lane < F3 - 32) op[lane + 32] = v1 - lse;
}

extern "C" void kernel_launch(void* const* d_in, const int* in_sizes, int n_in,
                              void* d_out, int out_size) {
    const float* x   = (const float*)d_in[0];
    const int*   ei  = (const int*)d_in[1];     // int32 (JAX x64 disabled)
    const float* W1  = (const float*)d_in[2];
    const float* b1  = (const float*)d_in[3];
    const float* W2  = (const float*)d_in[4];
    const float* b2  = (const float*)d_in[5];
    const float* W4  = (const float*)d_in[6];
    const float* b4  = (const float*)d_in[7];
    float* out = (float*)d_out;

    const int N = in_sizes[0] / F0;       // 100000
    const int E = in_sizes[1] / 2;        // 1600000
    const int* src = ei;
    const int* dst = ei + E;

    float *A, *B, *C;
    cudaGetSymbolAddress((void**)&A, g_bufA);
    cudaGetSymbolAddress((void**)&B, g_bufB);
    cudaGetSymbolAddress((void**)&C, g_bufC);

    // dynamic smem sizes for the pipelined GEMMs
    constexpr int SM128 = (2 * 128 * 36 + 2 * 32 * 132) * 4;   // 70656 B
    constexpr int SM64  = (2 * 128 * 36 + 2 * 32 * 68) * 4;    // 54272 B
    static bool attr_done = false;
    if (!attr_done) {
        cudaFuncSetAttribute(gemm_tf32_pipe_k<128>,
                             cudaFuncAttributeMaxDynamicSharedMemorySize, SM128);
        cudaFuncSetAttribute(gemm_tf32_pipe_k<64>,
                             cudaFuncAttributeMaxDynamicSharedMemorySize, SM64);
        attr_done = true;
    }

    // ---- CSR build + dinv ----
    cnt_init_k <<<(N + 255) / 256, 256>>>(N);
    cnt_count_k<<<(E + 255) / 256, 256>>>(dst, E);
    dinv_k     <<<(N + 255) / 256, 256>>>(N);
    scan1_k    <<<NBLK, SCAN_B>>>(N);
    scan2_k    <<<1, SCAN_B>>>(NBLK);
    scan3_k    <<<(N + 255) / 256, 256>>>(N);
    csr_fill_k <<<(E + 255) / 256, 256>>>(src, dst, E);

    // ---- layer 1: 500 -> 128 (tf32, pipelined) ----
    gemm_tf32_pipe_k<128><<<(N + 127) / 128, 256, SM128>>>(x, W1, A, N, F0);
    pull_k<128, 1><<<((size_t)N * 32 + 255) / 256, 256>>>(A, b1, B, N);

    // ---- layer 2: 128 -> 64 (tf32, pipelined) ----
    gemm_tf32_pipe_k<64><<<(N + 127) / 128, 256, SM64>>>(B, W2, A, N, F1);
    pull_k<64, 1><<<((size_t)N * 16 + 255) / 256, 256>>>(A, b2, B, N);

    // ---- layer 3: 64 -> 40 + log_softmax ----
    gemm_scale_k<128, 40, 16, 8, 5><<<(N + 127) / 128, 128>>>(B, W4, C, N, F2);
    pull_k<40, 0><<<((size_t)N * 10 + 255) / 256, 256>>>(C, (const float*)0, A, N);
    lsm_k<<<(N * 32 + 255) / 256, 256>>>(A, b4, out, N);
}

// round 7
// speedup vs baseline: 4.6737x; 1.0608x over previous
#include <cuda_runtime.h>
#include <cuda_fp16.h>
#include <math.h>

#define NN 100000
#define NE 1600000
#define F0 500
#define F1 128
#define F2 64
#define F3 40
#define SCAN_B 1024
#define NBLK ((NN + SCAN_B - 1) / SCAN_B)

// Static scratch (allocation-free rule: __device__ globals)
__device__ int   g_cnt [NN];
__device__ int   g_off [NN];
__device__ int   g_cur [NN];
__device__ int   g_bsum[SCAN_B];
__device__ int   g_csr [NE];
__device__ float g_dinv[NN];
__device__ __align__(16) __half g_h   [(size_t)NN * F1];   // fp16 hs (reused per layer)
__device__ __align__(16) float  g_bufA[(size_t)NN * F1];
__device__ __align__(16) float  g_bufB[(size_t)NN * F1];

// ---------------- degree / CSR build ----------------
__global__ void cnt_init_k(int n) {
    int i = blockIdx.x * blockDim.x + threadIdx.x;
    if (i < n) g_cnt[i] = 0;
}
__global__ void cnt_count_k(const int* __restrict__ dst, int e) {
    int i = blockIdx.x * blockDim.x + threadIdx.x;
    if (i < e) atomicAdd(&g_cnt[dst[i]], 1);
}
__global__ void dinv_k(int n) {
    int i = blockIdx.x * blockDim.x + threadIdx.x;
    if (i < n) g_dinv[i] = rsqrtf((float)(g_cnt[i] + 1));
}
__global__ void scan1_k(int n) {
    __shared__ int sh[SCAN_B];
    int t = threadIdx.x, g = blockIdx.x * SCAN_B + t;
    int v = (g < n) ? g_cnt[g] : 0;
    sh[t] = v; __syncthreads();
#pragma unroll
    for (int o = 1; o < SCAN_B; o <<= 1) {
        int x = (t >= o) ? sh[t - o] : 0;
        __syncthreads();
        sh[t] += x;
        __syncthreads();
    }
    if (g < n) g_off[g] = sh[t] - v;
    if (t == SCAN_B - 1) g_bsum[blockIdx.x] = sh[t];
}
__global__ void scan2_k(int nb) {
    __shared__ int sh[SCAN_B];
    int t = threadIdx.x;
    int v = (t < nb) ? g_bsum[t] : 0;
    sh[t] = v; __syncthreads();
#pragma unroll
    for (int o = 1; o < SCAN_B; o <<= 1) {
        int x = (t >= o) ? sh[t - o] : 0;
        __syncthreads();
        sh[t] += x;
        __syncthreads();
    }
    if (t < nb) g_bsum[t] = sh[t] - v;
}
__global__ void scan3_k(int n) {
    int i = blockIdx.x * blockDim.x + threadIdx.x;
    if (i < n) {
        int o = g_off[i] + g_bsum[i / SCAN_B];
        g_off[i] = o;
        g_cur[i] = o;
    }
}
__global__ void csr_fill_k(const int* __restrict__ src, const int* __restrict__ dst, int e) {
    int i = blockIdx.x * blockDim.x + threadIdx.x;
    if (i < e) {
        int pos = atomicAdd(&g_cur[dst[i]], 1);
        g_csr[pos] = src[i];
    }
}

// ---------------- tf32 helpers ----------------
__device__ __forceinline__ unsigned f2tf32(float x) {
    unsigned r;
    asm("cvt.rna.tf32.f32 %0, %1;" : "=r"(r) : "f"(x));
    return r;
}
__device__ __forceinline__ void mma_tf32(float* d, const unsigned* a, const unsigned* b) {
    asm volatile(
        "mma.sync.aligned.m16n8k8.row.col.f32.tf32.tf32.f32 "
        "{%0,%1,%2,%3},{%4,%5,%6,%7},{%8,%9},{%0,%1,%2,%3};"
        : "+f"(d[0]), "+f"(d[1]), "+f"(d[2]), "+f"(d[3])
        : "r"(a[0]), "r"(a[1]), "r"(a[2]), "r"(a[3]), "r"(b[0]), "r"(b[1]));
}
__device__ __forceinline__ void cp16(float* s, const float* g, bool pred) {
    unsigned sa = (unsigned)__cvta_generic_to_shared(s);
    int bytes = pred ? 16 : 0;
    asm volatile("cp.async.ca.shared.global [%0], [%1], 16, %2;"
                 :: "r"(sa), "l"(g), "r"(bytes));
}
#define CP_COMMIT() asm volatile("cp.async.commit_group;" ::: "memory")
#define CP_WAIT(N)  asm volatile("cp.async.wait_group %0;" :: "n"(N) : "memory")

// ---------------- pipelined tf32 GEMM, fp16 output ----------------
// hs_h[r,c] = half( (X[r,:] @ W[:,c]) * dinv[r] )
template<int BN>
__global__ void __launch_bounds__(256) gemm_tf32_pipe_k(
        const float* __restrict__ X, const float* __restrict__ W,
        __half* __restrict__ hs, int M, int K) {
    constexpr int BM = 128, BK = 32;
    constexpr int XSTR = BK + 4;
    constexpr int WSTR = BN + 4;
    constexpr int NJ = BN / 16;
    constexpr int XSZ = BM * XSTR;
    constexpr int WSZ = BK * WSTR;

    extern __shared__ float smem[];
    float* Xs0 = smem;
    float* Ws0 = smem + 2 * XSZ;

    const int tid    = threadIdx.x;
    const int lane   = tid & 31;
    const int wid    = tid >> 5;
    const int warp_m = wid & 3;
    const int warp_n = wid >> 2;
    const int row0   = blockIdx.x * BM;
    const int lq     = lane >> 2;
    const int lr     = lane & 3;

    float acc[2][NJ][4];
#pragma unroll
    for (int i = 0; i < 2; i++)
#pragma unroll
        for (int j = 0; j < NJ; j++)
#pragma unroll
            for (int t = 0; t < 4; t++) acc[i][j][t] = 0.f;

    const int nchunk = (K + BK - 1) / BK;

    auto load_tile = [&](int s, int k0) {
        float* Xs = Xs0 + s * XSZ;
        float* Ws = Ws0 + s * WSZ;
#pragma unroll
        for (int it = 0; it < 4; it++) {
            int idx = tid + it * 256;
            int r   = idx >> 3;
            int kv  = idx & 7;
            int gr  = row0 + r; if (gr >= M) gr = M - 1;
            bool p  = (k0 + kv * 4 + 4 <= K);
            int gk  = p ? (k0 + kv * 4) : 0;
            cp16(&Xs[r * XSTR + kv * 4], &X[(size_t)gr * K + gk], p);
        }
        constexpr int BIT = (BK * BN / 4) / 256;
#pragma unroll
        for (int it = 0; it < BIT; it++) {
            int idx = tid + it * 256;
            int kk  = idx / (BN / 4);
            int cv  = idx % (BN / 4);
            bool p  = (k0 + kk < K);
            int gk  = p ? (k0 + kk) : 0;
            cp16(&Ws[kk * WSTR + cv * 4], &W[(size_t)gk * BN + cv * 4], p);
        }
    };

    load_tile(0, 0);
    CP_COMMIT();

    for (int kc = 0; kc < nchunk; kc++) {
        const int s = kc & 1;
        if (kc + 1 < nchunk) {
            load_tile(s ^ 1, (kc + 1) * BK);
            CP_COMMIT();
            CP_WAIT(1);
        } else {
            CP_WAIT(0);
        }
        __syncthreads();

        const float* Xs = Xs0 + s * XSZ;
        const float* Ws = Ws0 + s * WSZ;
#pragma unroll
        for (int ks = 0; ks < 4; ks++) {
            const int kb = ks * 8;
            unsigned a[2][4], b[NJ][2];
#pragma unroll
            for (int i = 0; i < 2; i++) {
                int r = warp_m * 32 + i * 16;
                a[i][0] = f2tf32(Xs[(r + lq    ) * XSTR + kb + lr    ]);
                a[i][1] = f2tf32(Xs[(r + lq + 8) * XSTR + kb + lr    ]);
                a[i][2] = f2tf32(Xs[(r + lq    ) * XSTR + kb + lr + 4]);
                a[i][3] = f2tf32(Xs[(r + lq + 8) * XSTR + kb + lr + 4]);
            }
#pragma unroll
            for (int j = 0; j < NJ; j++) {
                int n = warp_n * (BN / 2) + j * 8 + lq;
                b[j][0] = f2tf32(Ws[(kb + lr    ) * WSTR + n]);
                b[j][1] = f2tf32(Ws[(kb + lr + 4) * WSTR + n]);
            }
#pragma unroll
            for (int i = 0; i < 2; i++)
#pragma unroll
                for (int j = 0; j < NJ; j++) mma_tf32(acc[i][j], a[i], b[j]);
        }
        __syncthreads();
    }

#pragma unroll
    for (int i = 0; i < 2; i++) {
        int r_lo = row0 + warp_m * 32 + i * 16 + lq;
        int r_hi = r_lo + 8;
        float dv_lo = (r_lo < M) ? g_dinv[r_lo] : 0.f;
        float dv_hi = (r_hi < M) ? g_dinv[r_hi] : 0.f;
#pragma unroll
        for (int j = 0; j < NJ; j++) {
            int c = warp_n * (BN / 2) + j * 8 + lr * 2;
            if (r_lo < M)
                *(__half2*)&hs[(size_t)r_lo * BN + c] =
                    __floats2half2_rn(acc[i][j][0] * dv_lo, acc[i][j][1] * dv_lo);
            if (r_hi < M)
                *(__half2*)&hs[(size_t)r_hi * BN + c] =
                    __floats2half2_rn(acc[i][j][2] * dv_hi, acc[i][j][3] * dv_hi);
        }
    }
}

// ---------------- fp32 GEMM for 64->40, fp16 output ----------------
template<int BM, int BN, int BK, int TM, int TN>
__global__ void gemm_scale_k(const float* __restrict__ X, const float* __restrict__ W,
                             __half* __restrict__ hs, int M, int K) {
    __shared__ float Xs[BM][BK + 1];
    __shared__ float Ws[BK][BN];
    constexpr int NT = (BM / TM) * (BN / TN);
    const int tid = threadIdx.x;
    const int tx  = tid % (BN / TN);
    const int ty  = tid / (BN / TN);
    const int row0 = blockIdx.x * BM;

    float acc[TM][TN];
#pragma unroll
    for (int i = 0; i < TM; i++)
#pragma unroll
        for (int j = 0; j < TN; j++) acc[i][j] = 0.f;

    for (int k0 = 0; k0 < K; k0 += BK) {
        for (int i = tid; i < BM * BK; i += NT) {
            int r = i / BK, kk = i % BK;
            int gr = row0 + r; if (gr >= M) gr = M - 1;
            int gk = k0 + kk;
            Xs[r][kk] = (gk < K) ? X[(size_t)gr * K + gk] : 0.f;
        }
        for (int i = tid; i < BK * BN; i += NT) {
            int kk = i / BN, c = i % BN;
            int gk = k0 + kk;
            Ws[kk][c] = (gk < K) ? W[(size_t)gk * BN + c] : 0.f;
        }
        __syncthreads();
#pragma unroll
        for (int kk = 0; kk < BK; kk++) {
            float a[TM], b[TN];
#pragma unroll
            for (int i = 0; i < TM; i++) a[i] = Xs[ty * TM + i][kk];
#pragma unroll
            for (int j = 0; j < TN; j++) b[j] = Ws[kk][tx * TN + j];
#pragma unroll
            for (int i = 0; i < TM; i++)
#pragma unroll
                for (int j = 0; j < TN; j++) acc[i][j] += a[i] * b[j];
        }
        __syncthreads();
    }

#pragma unroll
    for (int i = 0; i < TM; i++) {
        int r = row0 + ty * TM + i;
        if (r < M) {
            float dv = g_dinv[r];
#pragma unroll
            for (int j = 0; j < TN; j++)
                hs[(size_t)r * BN + tx * TN + j] = __float2half_rn(acc[i][j] * dv);
        }
    }
}

// ---------------- pull aggregation over fp16 hs ----------------
__device__ __forceinline__ void acc8(float* f, uint4 u) {
    float2 p0 = __half22float2(*(__half2*)&u.x);
    float2 p1 = __half22float2(*((__half2*)&u.x + 1));
    float2 p2 = __half22float2(*(__half2*)&u.z);
    float2 p3 = __half22float2(*((__half2*)&u.z + 1));
    f[0] += p0.x; f[1] += p0.y; f[2] += p1.x; f[3] += p1.y;
    f[4] += p2.x; f[5] += p2.y; f[6] += p3.x; f[7] += p3.y;
}

// thread (node, 8-feat chunk). EPI=1: relu(acc*dinv+b); EPI=0: raw acc.
template<int C, int EPI>
__global__ void pull_k(const __half* __restrict__ hs, const float* __restrict__ bias,
                       float* __restrict__ out, int n) {
    constexpr int CH8 = C / 8;
    int t = blockIdx.x * blockDim.x + threadIdx.x;
    int node = t / CH8;
    int c    = t % CH8;
    if (node >= n) return;

    const uint4* hs8 = (const uint4*)hs;
    float f[8] = {0, 0, 0, 0, 0, 0, 0, 0};
    acc8(f, hs8[(size_t)node * CH8 + c]);                  // self-loop
    int beg = g_off[node];
    int cnt = g_cnt[node];
    for (int i = 0; i < cnt; i++) {
        int s = g_csr[beg + i];
        acc8(f, hs8[(size_t)s * CH8 + c]);
    }
    size_t o = (size_t)node * C + c * 8;
    if (EPI) {
        float dv = g_dinv[node];
        float4 b0 = ((const float4*)bias)[c * 2];
        float4 b1 = ((const float4*)bias)[c * 2 + 1];
        float4 v0 = make_float4(fmaxf(f[0] * dv + b0.x, 0.f), fmaxf(f[1] * dv + b0.y, 0.f),
                                fmaxf(f[2] * dv + b0.z, 0.f), fmaxf(f[3] * dv + b0.w, 0.f));
        float4 v1 = make_float4(fmaxf(f[4] * dv + b1.x, 0.f), fmaxf(f[5] * dv + b1.y, 0.f),
                                fmaxf(f[6] * dv + b1.z, 0.f), fmaxf(f[7] * dv + b1.w, 0.f));
        *(float4*)&out[o]     = v0;
        *(float4*)&out[o + 4] = v1;
    } else {
        *(float4*)&out[o]     = make_float4(f[0], f[1], f[2], f[3]);
        *(float4*)&out[o + 4] = make_float4(f[4], f[5], f[6], f[7]);
    }
}

// ---------------- final layer: dinv + bias + log_softmax ----------------
__global__ void lsm_k(const float* __restrict__ agg, const float* __restrict__ b,
                      float* __restrict__ out, int n) {
    int gid  = blockIdx.x * blockDim.x + threadIdx.x;
    int row  = gid >> 5;
    int lane = threadIdx.x & 31;
    if (row >= n) return;
    float dv = g_dinv[row];
    const float* rp = agg + (size_t)row * F3;
    float v0 = rp[lane] * dv + b[lane];
    float v1 = (lane < F3 - 32) ? rp[lane + 32] * dv + b[lane + 32] : -INFINITY;
    float m = fmaxf(v0, v1);
#pragma unroll
    for (int o = 16; o; o >>= 1) m = fmaxf(m, __shfl_xor_sync(0xffffffffu, m, o));
    float s = expf(v0 - m) + ((lane < F3 - 32) ? expf(v1 - m) : 0.f);
#pragma unroll
    for (int o = 16; o; o >>= 1) s += __shfl_xor_sync(0xffffffffu, s, o);
    float lse = logf(s) + m;
    float* op = out + (size_t)row * F3;
    op[lane] = v0 - lse;
    if (lane < F3 - 32) op[lane + 32] = v1 - lse;
}

extern "C" void kernel_launch(void* const* d_in, const int* in_sizes, int n_in,
                              void* d_out, int out_size) {
    const float* x   = (const float*)d_in[0];
    const int*   ei  = (const int*)d_in[1];     // int32 (JAX x64 disabled)
    const float* W1  = (const float*)d_in[2];
    const float* b1  = (const float*)d_in[3];
    const float* W2  = (const float*)d_in[4];
    const float* b2  = (const float*)d_in[5];
    const float* W4  = (const float*)d_in[6];
    const float* b4  = (const float*)d_in[7];
    float* out = (float*)d_out;

    const int N = in_sizes[0] / F0;       // 100000
    const int E = in_sizes[1] / 2;        // 1600000
    const int* src = ei;
    const int* dst = ei + E;

    float *A, *B;
    __half* H;
    cudaGetSymbolAddress((void**)&A, g_bufA);
    cudaGetSymbolAddress((void**)&B, g_bufB);
    cudaGetSymbolAddress((void**)&H, g_h);

    constexpr int SM128 = (2 * 128 * 36 + 2 * 32 * 132) * 4;
    constexpr int SM64  = (2 * 128 * 36 + 2 * 32 * 68) * 4;
    static bool attr_done = false;
    if (!attr_done) {
        cudaFuncSetAttribute(gemm_tf32_pipe_k<128>,
                             cudaFuncAttributeMaxDynamicSharedMemorySize, SM128);
        cudaFuncSetAttribute(gemm_tf32_pipe_k<64>,
                             cudaFuncAttributeMaxDynamicSharedMemorySize, SM64);
        attr_done = true;
    }

    // ---- CSR build + dinv ----
    cnt_init_k <<<(N + 255) / 256, 256>>>(N);
    cnt_count_k<<<(E + 255) / 256, 256>>>(dst, E);
    dinv_k     <<<(N + 255) / 256, 256>>>(N);
    scan1_k    <<<NBLK, SCAN_B>>>(N);
    scan2_k    <<<1, SCAN_B>>>(NBLK);
    scan3_k    <<<(N + 255) / 256, 256>>>(N);
    csr_fill_k <<<(E + 255) / 256, 256>>>(src, dst, E);

    // ---- layer 1: 500 -> 128 ----
    gemm_tf32_pipe_k<128><<<(N + 127) / 128, 256, SM128>>>(x, W1, H, N, F0);
    pull_k<128, 1><<<((size_t)N * 16 + 255) / 256, 256>>>(H, b1, A, N);

    // ---- layer 2: 128 -> 64 ----
    gemm_tf32_pipe_k<64><<<(N + 127) / 128, 256, SM64>>>(A, W2, H, N, F1);
    pull_k<64, 1><<<((size_t)N * 8 + 255) / 256, 256>>>(H, b2, B, N);

    // ---- layer 3: 64 -> 40 + log_softmax ----
    gemm_scale_k<128, 40, 16, 8, 5><<<(N + 127) / 128, 128>>>(B, W4, H, N, F2);
    pull_k<40, 0><<<((size_t)N * 5 + 255) / 256, 256>>>(H, (const float*)0, A, N);
    lsm_k<<<(N * 32 + 255) / 256, 256>>>(A, b4, out, N);
}

// round 8
// speedup vs baseline: 4.8459x; 1.0369x over previous
#include <cuda_runtime.h>
#include <cuda_fp16.h>
#include <math.h>

#define NN 100000
#define NE 1600000
#define F0 500
#define F1 128
#define F2 64
#define F3 40
#define SCAN_B 1024
#define NBLK ((NN + SCAN_B - 1) / SCAN_B)

// Static scratch (allocation-free rule: __device__ globals)
__device__ int   g_cnt [NN];
__device__ int   g_off [NN];
__device__ int   g_cur [NN];
__device__ int   g_bsum[SCAN_B];
__device__ int   g_csr [NE];
__device__ float g_dinv[NN];
__device__ __align__(16) __half g_h [(size_t)NN * F1];   // GEMM outputs (fp16)
__device__ __align__(16) __half g_h2[(size_t)NN * F1];   // pull outputs (fp16)
__device__ __align__(16) float  g_bufA[(size_t)NN * F1]; // pull3 out (fp32)

// ---------------- degree / CSR build ----------------
__global__ void cnt_init_k(int n) {
    int i = blockIdx.x * blockDim.x + threadIdx.x;
    if (i < n) g_cnt[i] = 0;
}
__global__ void cnt_count_k(const int* __restrict__ dst, int e) {
    int i = blockIdx.x * blockDim.x + threadIdx.x;
    if (i < e) atomicAdd(&g_cnt[dst[i]], 1);
}
__global__ void dinv_k(int n) {
    int i = blockIdx.x * blockDim.x + threadIdx.x;
    if (i < n) g_dinv[i] = rsqrtf((float)(g_cnt[i] + 1));
}
__global__ void scan1_k(int n) {
    __shared__ int sh[SCAN_B];
    int t = threadIdx.x, g = blockIdx.x * SCAN_B + t;
    int v = (g < n) ? g_cnt[g] : 0;
    sh[t] = v; __syncthreads();
#pragma unroll
    for (int o = 1; o < SCAN_B; o <<= 1) {
        int x = (t >= o) ? sh[t - o] : 0;
        __syncthreads();
        sh[t] += x;
        __syncthreads();
    }
    if (g < n) g_off[g] = sh[t] - v;
    if (t == SCAN_B - 1) g_bsum[blockIdx.x] = sh[t];
}
__global__ void scan2_k(int nb) {
    __shared__ int sh[SCAN_B];
    int t = threadIdx.x;
    int v = (t < nb) ? g_bsum[t] : 0;
    sh[t] = v; __syncthreads();
#pragma unroll
    for (int o = 1; o < SCAN_B; o <<= 1) {
        int x = (t >= o) ? sh[t - o] : 0;
        __syncthreads();
        sh[t] += x;
        __syncthreads();
    }
    if (t < nb) g_bsum[t] = sh[t] - v;
}
__global__ void scan3_k(int n) {
    int i = blockIdx.x * blockDim.x + threadIdx.x;
    if (i < n) {
        int o = g_off[i] + g_bsum[i / SCAN_B];
        g_off[i] = o;
        g_cur[i] = o;
    }
}
__global__ void csr_fill_k(const int* __restrict__ src, const int* __restrict__ dst, int e) {
    int i = blockIdx.x * blockDim.x + threadIdx.x;
    if (i < e) {
        int pos = atomicAdd(&g_cur[dst[i]], 1);
        g_csr[pos] = src[i];
    }
}

// ---------------- tf32 helpers ----------------
__device__ __forceinline__ unsigned f2tf32(float x) {
    unsigned r;
    asm("cvt.rna.tf32.f32 %0, %1;" : "=r"(r) : "f"(x));
    return r;
}
__device__ __forceinline__ unsigned ld_tf32(const float* p)  { return f2tf32(*p); }
__device__ __forceinline__ unsigned ld_tf32(const __half* p) { return f2tf32(__half2float(*p)); }
__device__ __forceinline__ void mma_tf32(float* d, const unsigned* a, const unsigned* b) {
    asm volatile(
        "mma.sync.aligned.m16n8k8.row.col.f32.tf32.tf32.f32 "
        "{%0,%1,%2,%3},{%4,%5,%6,%7},{%8,%9},{%0,%1,%2,%3};"
        : "+f"(d[0]), "+f"(d[1]), "+f"(d[2]), "+f"(d[3])
        : "r"(a[0]), "r"(a[1]), "r"(a[2]), "r"(a[3]), "r"(b[0]), "r"(b[1]));
}
template<typename T>
__device__ __forceinline__ void cp16(T* s, const T* g, bool pred) {
    unsigned sa = (unsigned)__cvta_generic_to_shared(s);
    int bytes = pred ? 16 : 0;
    asm volatile("cp.async.ca.shared.global [%0], [%1], 16, %2;"
                 :: "r"(sa), "l"(g), "r"(bytes));
}
#define CP_COMMIT() asm volatile("cp.async.commit_group;" ::: "memory")
#define CP_WAIT(N)  asm volatile("cp.async.wait_group %0;" :: "n"(N) : "memory")

// ---------------- pipelined tf32 GEMM, TI input (float/half), fp16 out ----
template<int BN, typename TI>
__global__ void __launch_bounds__(256) gemm_tf32_pipe_k(
        const TI* __restrict__ X, const float* __restrict__ W,
        __half* __restrict__ hs, int M, int K) {
    constexpr int BM = 128, BK = 32;
    constexpr int EPC  = 16 / (int)sizeof(TI);             // elems per 16B chunk
    constexpr int XSTR = (sizeof(TI) == 4) ? (BK + 4) : (BK + 16);  // 16B-mult rows
    constexpr int WSTR = BN + 4;
    constexpr int NJ = BN / 16;
    constexpr int XSZ = BM * XSTR;                         // TI elems
    constexpr int WSZ = BK * WSTR;                         // floats

    extern __shared__ char smraw[];
    TI*    Xs0 = (TI*)smraw;
    float* Ws0 = (float*)(smraw + 2 * XSZ * sizeof(TI));

    const int tid    = threadIdx.x;
    const int lane   = tid & 31;
    const int wid    = tid >> 5;
    const int warp_m = wid & 3;
    const int warp_n = wid >> 2;
    const int row0   = blockIdx.x * BM;
    const int lq     = lane >> 2;
    const int lr     = lane & 3;

    float acc[2][NJ][4];
#pragma unroll
    for (int i = 0; i < 2; i++)
#pragma unroll
        for (int j = 0; j < NJ; j++)
#pragma unroll
            for (int t = 0; t < 4; t++) acc[i][j][t] = 0.f;

    const int nchunk = (K + BK - 1) / BK;

    auto load_tile = [&](int s, int k0) {
        TI*    Xs = Xs0 + s * XSZ;
        float* Ws = Ws0 + s * WSZ;
        constexpr int AIT = (BM * BK / EPC) / 256;
#pragma unroll
        for (int it = 0; it < AIT; it++) {
            int idx = tid + it * 256;
            int r   = idx / (BK / EPC);
            int kv  = idx % (BK / EPC);
            int gr  = row0 + r; if (gr >= M) gr = M - 1;
            bool p  = (k0 + kv * EPC + EPC <= K);
            int gk  = p ? (k0 + kv * EPC) : 0;
            cp16(&Xs[r * XSTR + kv * EPC], &X[(size_t)gr * K + gk], p);
        }
        constexpr int BIT = (BK * BN / 4) / 256;
#pragma unroll
        for (int it = 0; it < BIT; it++) {
            int idx = tid + it * 256;
            int kk  = idx / (BN / 4);
            int cv  = idx % (BN / 4);
            bool p  = (k0 + kk < K);
            int gk  = p ? (k0 + kk) : 0;
            cp16(&Ws[kk * WSTR + cv * 4], &W[(size_t)gk * BN + cv * 4], p);
        }
    };

    load_tile(0, 0);
    CP_COMMIT();

    for (int kc = 0; kc < nchunk; kc++) {
        const int s = kc & 1;
        if (kc + 1 < nchunk) {
            load_tile(s ^ 1, (kc + 1) * BK);
            CP_COMMIT();
            CP_WAIT(1);
        } else {
            CP_WAIT(0);
        }
        __syncthreads();

        const TI*    Xs = Xs0 + s * XSZ;
        const float* Ws = Ws0 + s * WSZ;
#pragma unroll
        for (int ks = 0; ks < 4; ks++) {
            const int kb = ks * 8;
            unsigned a[2][4], b[NJ][2];
#pragma unroll
            for (int i = 0; i < 2; i++) {
                int r = warp_m * 32 + i * 16;
                a[i][0] = ld_tf32(&Xs[(r + lq    ) * XSTR + kb + lr    ]);
                a[i][1] = ld_tf32(&Xs[(r + lq + 8) * XSTR + kb + lr    ]);
                a[i][2] = ld_tf32(&Xs[(r + lq    ) * XSTR + kb + lr + 4]);
                a[i][3] = ld_tf32(&Xs[(r + lq + 8) * XSTR + kb + lr + 4]);
            }
#pragma unroll
            for (int j = 0; j < NJ; j++) {
                int n = warp_n * (BN / 2) + j * 8 + lq;
                b[j][0] = ld_tf32(&Ws[(kb + lr    ) * WSTR + n]);
                b[j][1] = ld_tf32(&Ws[(kb + lr + 4) * WSTR + n]);
            }
#pragma unroll
            for (int i = 0; i < 2; i++)
#pragma unroll
                for (int j = 0; j < NJ; j++) mma_tf32(acc[i][j], a[i], b[j]);
        }
        __syncthreads();
    }

#pragma unroll
    for (int i = 0; i < 2; i++) {
        int r_lo = row0 + warp_m * 32 + i * 16 + lq;
        int r_hi = r_lo + 8;
        float dv_lo = (r_lo < M) ? g_dinv[r_lo] : 0.f;
        float dv_hi = (r_hi < M) ? g_dinv[r_hi] : 0.f;
#pragma unroll
        for (int j = 0; j < NJ; j++) {
            int c = warp_n * (BN / 2) + j * 8 + lr * 2;
            if (r_lo < M)
                *(__half2*)&hs[(size_t)r_lo * BN + c] =
                    __floats2half2_rn(acc[i][j][0] * dv_lo, acc[i][j][1] * dv_lo);
            if (r_hi < M)
                *(__half2*)&hs[(size_t)r_hi * BN + c] =
                    __floats2half2_rn(acc[i][j][2] * dv_hi, acc[i][j][3] * dv_hi);
        }
    }
}

// ---------------- fp32 GEMM for 64->40, half in / half out ----------------
template<int BM, int BN, int BK, int TM, int TN>
__global__ void gemm_scale_k(const __half* __restrict__ X, const float* __restrict__ W,
                             __half* __restrict__ hs, int M, int K) {
    __shared__ float Xs[BM][BK + 1];
    __shared__ float Ws[BK][BN];
    constexpr int NT = (BM / TM) * (BN / TN);
    const int tid = threadIdx.x;
    const int tx  = tid % (BN / TN);
    const int ty  = tid / (BN / TN);
    const int row0 = blockIdx.x * BM;

    float acc[TM][TN];
#pragma unroll
    for (int i = 0; i < TM; i++)
#pragma unroll
        for (int j = 0; j < TN; j++) acc[i][j] = 0.f;

    for (int k0 = 0; k0 < K; k0 += BK) {
        for (int i = tid; i < BM * BK; i += NT) {
            int r = i / BK, kk = i % BK;
            int gr = row0 + r; if (gr >= M) gr = M - 1;
            int gk = k0 + kk;
            Xs[r][kk] = (gk < K) ? __half2float(X[(size_t)gr * K + gk]) : 0.f;
        }
        for (int i = tid; i < BK * BN; i += NT) {
            int kk = i / BN, c = i % BN;
            int gk = k0 + kk;
            Ws[kk][c] = (gk < K) ? W[(size_t)gk * BN + c] : 0.f;
        }
        __syncthreads();
#pragma unroll
        for (int kk = 0; kk < BK; kk++) {
            float a[TM], b[TN];
#pragma unroll
            for (int i = 0; i < TM; i++) a[i] = Xs[ty * TM + i][kk];
#pragma unroll
            for (int j = 0; j < TN; j++) b[j] = Ws[kk][tx * TN + j];
#pragma unroll
            for (int i = 0; i < TM; i++)
#pragma unroll
                for (int j = 0; j < TN; j++) acc[i][j] += a[i] * b[j];
        }
        __syncthreads();
    }

#pragma unroll
    for (int i = 0; i < TM; i++) {
        int r = row0 + ty * TM + i;
        if (r < M) {
            float dv = g_dinv[r];
#pragma unroll
            for (int j = 0; j < TN; j++)
                hs[(size_t)r * BN + tx * TN + j] = __float2half_rn(acc[i][j] * dv);
        }
    }
}

// ---------------- pull aggregation over fp16 hs ----------------
__device__ __forceinline__ void acc8(float* f, uint4 u) {
    float2 p0 = __half22float2(*(__half2*)&u.x);
    float2 p1 = __half22float2(*((__half2*)&u.x + 1));
    float2 p2 = __half22float2(*(__half2*)&u.z);
    float2 p3 = __half22float2(*((__half2*)&u.z + 1));
    f[0] += p0.x; f[1] += p0.y; f[2] += p1.x; f[3] += p1.y;
    f[4] += p2.x; f[5] += p2.y; f[6] += p3.x; f[7] += p3.y;
}

// thread (node, 8-feat chunk). EPI=1: half out = relu(acc*dinv+b); EPI=0: float out = acc.
template<int C, int EPI, typename TO>
__global__ void pull_k(const __half* __restrict__ hs, const float* __restrict__ bias,
                       TO* __restrict__ out, int n) {
    constexpr int CH8 = C / 8;
    int t = blockIdx.x * blockDim.x + threadIdx.x;
    int node = t / CH8;
    int c    = t % CH8;
    if (node >= n) return;

    const uint4* hs8 = (const uint4*)hs;
    float f[8] = {0, 0, 0, 0, 0, 0, 0, 0};
    acc8(f, hs8[(size_t)node * CH8 + c]);                  // self-loop
    int beg = g_off[node];
    int cnt = g_cnt[node];
    for (int i = 0; i < cnt; i++) {
        int s = g_csr[beg + i];
        acc8(f, hs8[(size_t)s * CH8 + c]);
    }
    if (EPI) {
        float dv = g_dinv[node];
        float4 b0 = ((const float4*)bias)[c * 2];
        float4 b1 = ((const float4*)bias)[c * 2 + 1];
        float v0 = fmaxf(f[0] * dv + b0.x, 0.f), v1 = fmaxf(f[1] * dv + b0.y, 0.f);
        float v2 = fmaxf(f[2] * dv + b0.z, 0.f), v3 = fmaxf(f[3] * dv + b0.w, 0.f);
        float v4 = fmaxf(f[4] * dv + b1.x, 0.f), v5 = fmaxf(f[5] * dv + b1.y, 0.f);
        float v6 = fmaxf(f[6] * dv + b1.z, 0.f), v7 = fmaxf(f[7] * dv + b1.w, 0.f);
        uint4 u;
        *(__half2*)&u.x = __floats2half2_rn(v0, v1);
        *((__half2*)&u.x + 1) = __floats2half2_rn(v2, v3);
        *(__half2*)&u.z = __floats2half2_rn(v4, v5);
        *((__half2*)&u.z + 1) = __floats2half2_rn(v6, v7);
        ((uint4*)out)[(size_t)node * CH8 + c] = u;
    } else {
        size_t o = (size_t)node * C + c * 8;
        *(float4*)&((float*)out)[o]     = make_float4(f[0], f[1], f[2], f[3]);
        *(float4*)&((float*)out)[o + 4] = make_float4(f[4], f[5], f[6], f[7]);
    }
}

// ---------------- final layer: dinv + bias + log_softmax ----------------
__global__ void lsm_k(const float* __restrict__ agg, const float* __restrict__ b,
                      float* __restrict__ out, int n) {
    int gid  = blockIdx.x * blockDim.x + threadIdx.x;
    int row  = gid >> 5;
    int lane = threadIdx.x & 31;
    if (row >= n) return;
    float dv = g_dinv[row];
    const float* rp = agg + (size_t)row * F3;
    float v0 = rp[lane] * dv + b[lane];
    float v1 = (lane < F3 - 32) ? rp[lane + 32] * dv + b[lane + 32] : -INFINITY;
    float m = fmaxf(v0, v1);
#pragma unroll
    for (int o = 16; o; o >>= 1) m = fmaxf(m, __shfl_xor_sync(0xffffffffu, m, o));
    float s = expf(v0 - m) + ((lane < F3 - 32) ? expf(v1 - m) : 0.f);
#pragma unroll
    for (int o = 16; o; o >>= 1) s += __shfl_xor_sync(0xffffffffu, s, o);
    float lse = logf(s) + m;
    float* op = out + (size_t)row * F3;
    op[lane] = v0 - lse;
    if (lane < F3 - 32) op[lane + 32] = v1 - lse;
}

extern "C" void kernel_launch(void* const* d_in, const int* in_sizes, int n_in,
                              void* d_out, int out_size) {
    const float* x   = (const float*)d_in[0];
    const int*   ei  = (const int*)d_in[1];     // int32 (JAX x64 disabled)
    const float* W1  = (const float*)d_in[2];
    const float* b1  = (const float*)d_in[3];
    const float* W2  = (const float*)d_in[4];
    const float* b2  = (const float*)d_in[5];
    const float* W4  = (const float*)d_in[6];
    const float* b4  = (const float*)d_in[7];
    float* out = (float*)d_out;

    const int N = in_sizes[0] / F0;       // 100000
    const int E = in_sizes[1] / 2;        // 1600000
    const int* src = ei;
    const int* dst = ei + E;

    float*  A;
    __half *H, *H2;
    cudaGetSymbolAddress((void**)&A,  g_bufA);
    cudaGetSymbolAddress((void**)&H,  g_h);
    cudaGetSymbolAddress((void**)&H2, g_h2);

    constexpr int SM128F = (2 * 128 * 36 + 2 * 32 * 132) * 4;          // 70656 B
    constexpr int SM64H  = 2 * 128 * 48 * 2 + 2 * 32 * 68 * 4;         // 41984 B

    static cudaStream_t sM = nullptr, sS = nullptr;
    static cudaEvent_t  evF = nullptr, evS = nullptr, evJ = nullptr;
    if (!sM) {
        cudaStreamCreateWithFlags(&sM, cudaStreamNonBlocking);
        cudaStreamCreateWithFlags(&sS, cudaStreamNonBlocking);
        cudaEventCreateWithFlags(&evF, cudaEventDisableTiming);
        cudaEventCreateWithFlags(&evS, cudaEventDisableTiming);
        cudaEventCreateWithFlags(&evJ, cudaEventDisableTiming);
        cudaFuncSetAttribute(gemm_tf32_pipe_k<128, float>,
                             cudaFuncAttributeMaxDynamicSharedMemorySize, SM128F);
        cudaFuncSetAttribute(gemm_tf32_pipe_k<64, __half>,
                             cudaFuncAttributeMaxDynamicSharedMemorySize, SM64H);
    }

    // ---- prologue on the capture stream: degree + dinv (GEMM1 needs dinv) ----
    cnt_init_k <<<(N + 255) / 256, 256>>>(N);
    cnt_count_k<<<(E + 255) / 256, 256>>>(dst, E);
    dinv_k     <<<(N + 255) / 256, 256>>>(N);

    // ---- fork: CSR tail on sS concurrent with GEMM1 on sM ----
    cudaEventRecord(evF, 0);
    cudaStreamWaitEvent(sM, evF, 0);
    cudaStreamWaitEvent(sS, evF, 0);

    scan1_k   <<<NBLK, SCAN_B, 0, sS>>>(N);
    scan2_k   <<<1, SCAN_B, 0, sS>>>(NBLK);
    scan3_k   <<<(N + 255) / 256, 256, 0, sS>>>(N);
    csr_fill_k<<<(E + 255) / 256, 256, 0, sS>>>(src, dst, E);

    gemm_tf32_pipe_k<128, float><<<(N + 127) / 128, 256, SM128F, sM>>>(x, W1, H, N, F0);

    // ---- join: pull1 needs CSR + GEMM1 ----
    cudaEventRecord(evS, sS);
    cudaStreamWaitEvent(sM, evS, 0);

    pull_k<128, 1, __half><<<((size_t)N * 16 + 255) / 256, 256, 0, sM>>>(H, b1, H2, N);

    gemm_tf32_pipe_k<64, __half><<<(N + 127) / 128, 256, SM64H, sM>>>(H2, W2, H, N, F1);
    pull_k<64, 1, __half><<<((size_t)N * 8 + 255) / 256, 256, 0, sM>>>(H, b2, H2, N);

    gemm_scale_k<128, 40, 16, 8, 5><<<(N + 127) / 128, 128, 0, sM>>>(H2, W4, H, N, F2);
    pull_k<40, 0, float><<<((size_t)N * 5 + 255) / 256, 256, 0, sM>>>(H, (const float*)0, A, N);
    lsm_k<<<(N * 32 + 255) / 256, 256, 0, sM>>>(A, b4, out, N);

    // ---- join back to the capture stream ----
    cudaEventRecord(evJ, sM);
    cudaStreamWaitEvent(0, evJ, 0);
}